// round 12
// baseline (speedup 1.0000x reference)
#include <cuda_runtime.h>
#include <cuda_bf16.h>
#include <cuda_fp16.h>
#include <cstdint>

// ---------------------------------------------------------------------------
// 2-layer GCN. R12 = R11 with the fork moved: dense prep overlaps ONLY k_csr
// (k_scan runs uncontended). Pipeline:
//   init -> deg -> scan -> fork{ csr || prepd } -> gather1(c0)
//   -> { gather1(c1) || GEMM1(c0),GEMM2(c0) } -> GEMM(c1) -> gather2
// ---------------------------------------------------------------------------

static constexpr int NNODES = 50000;
static constexpr int NEDGES = 800000;
static constexpr int INDIM  = 128;
static constexpr int ADDDIM = 8;
static constexpr int HID    = 256;
static constexpr int OUTD   = 128;
static constexpr int CHUNK0 = 25088;                  // 196 * 128

// -------------------- device scratch ----------------------------------------
__device__ __align__(16) __half g_xh[(size_t)NNODES * INDIM];
__device__ __align__(16) __nv_bfloat16 g_aggx_hi[(size_t)NNODES * INDIM];
__device__ __align__(16) __nv_bfloat16 g_aggx_lo[(size_t)NNODES * INDIM];
__device__ __align__(16) __nv_bfloat16 g_h1_hi[(size_t)NNODES * HID];
__device__ __align__(16) __nv_bfloat16 g_h1_lo[(size_t)NNODES * HID];
__device__ __align__(16) __half g_h2[(size_t)NNODES * OUTD];
__device__ float g_q[NNODES];
__device__ float g_dinv[NNODES];
__device__ int   g_deg[NNODES];
__device__ int   g_off[NNODES + 1];
__device__ int   g_cur[NNODES];
__device__ int   g_src[NEDGES];
__device__ float g_c1[HID];
__device__ __align__(16) __nv_bfloat16 g_wt1_hi[HID * INDIM], g_wt1_lo[HID * INDIM];
__device__ __align__(16) __nv_bfloat16 g_wt2_hi[OUTD * HID],  g_wt2_lo[OUTD * HID];
__device__ int g_is64;

// -------------------- asm helpers -------------------------------------------
__device__ __forceinline__ uint32_t smem_u32(const void* p) {
    return (uint32_t)__cvta_generic_to_shared(p);
}
__device__ __forceinline__ void ldsm_x4(uint32_t r[4], uint32_t addr) {
    asm volatile("ldmatrix.sync.aligned.m8n8.x4.shared.b16 {%0,%1,%2,%3}, [%4];"
                 : "=r"(r[0]), "=r"(r[1]), "=r"(r[2]), "=r"(r[3]) : "r"(addr));
}
__device__ __forceinline__ void mma_bf16(float* c, const uint32_t* a,
                                         uint32_t b0, uint32_t b1) {
    asm volatile(
        "mma.sync.aligned.m16n8k16.row.col.f32.bf16.bf16.f32 "
        "{%0,%1,%2,%3}, {%4,%5,%6,%7}, {%8,%9}, {%0,%1,%2,%3};"
        : "+f"(c[0]), "+f"(c[1]), "+f"(c[2]), "+f"(c[3])
        : "r"(a[0]), "r"(a[1]), "r"(a[2]), "r"(a[3]), "r"(b0), "r"(b1));
}
__device__ __forceinline__ void cp16(uint32_t dst, const void* src, uint32_t sz) {
    asm volatile("cp.async.cg.shared.global [%0], [%1], 16, %2;"
                 :: "r"(dst), "l"(src), "r"(sz) : "memory");
}
__device__ __forceinline__ void cp_commit() {
    asm volatile("cp.async.commit_group;" ::: "memory");
}
template <int N>
__device__ __forceinline__ void cp_wait() {
    asm volatile("cp.async.wait_group %0;" :: "n"(N) : "memory");
}

// -------------------- prep kernels ------------------------------------------
__global__ void k_init(const long long* __restrict__ ei) {
    int i = blockIdx.x * blockDim.x + threadIdx.x;
    if (i < NNODES) g_deg[i] = 0;
    if (blockIdx.x == 0 && threadIdx.x < 32) {
        bool bad = false;
        for (int j = threadIdx.x; j < 512; j += 32) {
            long long v = ei[j];
            if (v < 0 || v >= NNODES) bad = true;
        }
        unsigned m = __ballot_sync(0xFFFFFFFFu, bad);
        if (threadIdx.x == 0) g_is64 = (m == 0u) ? 1 : 0;
    }
}
// dense prep: x->fp16, weight split+transpose, c1
__global__ void k_prepd(const float* __restrict__ x,
                        const float* __restrict__ W1, const float* __restrict__ W2,
                        const float* __restrict__ idv) {
    constexpr int XT = NNODES * INDIM / 4;
    constexpr int N1 = HID * INDIM;
    constexpr int N2 = OUTD * HID;
    int idx = blockIdx.x * blockDim.x + threadIdx.x;
    if (idx < XT) {
        float4 v = __ldg((const float4*)x + idx);
        __half2 p0 = __floats2half2_rn(v.x, v.y);
        __half2 p1 = __floats2half2_rn(v.z, v.w);
        uint2 o;
        o.x = *(uint32_t*)&p0;
        o.y = *(uint32_t*)&p1;
        *((uint2*)g_xh + idx) = o;
    } else if (idx < XT + N1) {
        int j = idx - XT;
        int o = j / INDIM, i = j % INDIM;
        float v = W1[(size_t)i * HID + o];
        __nv_bfloat16 h = __float2bfloat16_rn(v);
        g_wt1_hi[j] = h;
        g_wt1_lo[j] = __float2bfloat16_rn(v - __bfloat162float(h));
    } else if (idx < XT + N1 + N2) {
        int j = idx - XT - N1;
        int o = j / HID, i = j % HID;
        float v = W2[(size_t)i * OUTD + o];
        __nv_bfloat16 h = __float2bfloat16_rn(v);
        g_wt2_hi[j] = h;
        g_wt2_lo[j] = __float2bfloat16_rn(v - __bfloat162float(h));
    } else if (idx < XT + N1 + N2 + HID) {
        int j = idx - XT - N1 - N2;
        float s = 0.f;
#pragma unroll
        for (int t = 0; t < ADDDIM; t++) s += idv[t] * W1[(size_t)(INDIM + t) * HID + j];
        g_c1[j] = s;
    }
}

__global__ void k_deg(const void* __restrict__ ei) {
    int i = blockIdx.x * blockDim.x + threadIdx.x;
    if (i >= NEDGES / 2) return;
    int d0, d1;
    if (g_is64) {
        longlong2 v = __ldg((const longlong2*)ei + NEDGES / 2 + i);
        d0 = (int)v.x; d1 = (int)v.y;
    } else {
        int2 v = __ldg((const int2*)ei + NEDGES / 2 + i);
        d0 = v.x; d1 = v.y;
    }
    atomicAdd(&g_deg[d0], 1);
    atomicAdd(&g_deg[d1], 1);
}
__global__ void k_scan() {
    __shared__ int warpsum[32];
    __shared__ int chunk_total;
    const int t = threadIdx.x;               // 1024
    const int lane = t & 31, wid = t >> 5;
    int run = 0;
    for (int base = 0; base < NNODES; base += 2048) {
        int i0 = base + t * 2, i1 = i0 + 1;
        int v0 = (i0 < NNODES) ? g_deg[i0] : 0;
        int v1 = (i1 < NNODES) ? g_deg[i1] : 0;
        if (i0 < NNODES) g_dinv[i0] = rsqrtf((float)(v0 + 1));
        if (i1 < NNODES) g_dinv[i1] = rsqrtf((float)(v1 + 1));
        int v = v0 + v1;
        int x = v;
#pragma unroll
        for (int o = 1; o < 32; o <<= 1) {
            int y = __shfl_up_sync(0xFFFFFFFFu, x, o);
            if (lane >= o) x += y;
        }
        if (lane == 31) warpsum[wid] = x;
        __syncthreads();
        if (wid == 0) {
            int w = warpsum[lane];
#pragma unroll
            for (int o = 1; o < 32; o <<= 1) {
                int y = __shfl_up_sync(0xFFFFFFFFu, w, o);
                if (lane >= o) w += y;
            }
            warpsum[lane] = w;
            if (lane == 31) chunk_total = w;
        }
        __syncthreads();
        int excl = run + (wid ? warpsum[wid - 1] : 0) + x - v;
        if (i0 < NNODES) { g_off[i0] = excl; g_cur[i0] = excl; }
        if (i1 < NNODES) { g_off[i1] = excl + v0; g_cur[i1] = excl + v0; }
        run += chunk_total;
        __syncthreads();
    }
    if (t == 0) g_off[NNODES] = run;
}
__global__ void k_csr(const void* __restrict__ ei) {
    int i = blockIdx.x * blockDim.x + threadIdx.x;
    if (i >= NEDGES / 2) return;
    int s0, s1, d0, d1;
    if (g_is64) {
        longlong2 sv = __ldg((const longlong2*)ei + i);
        longlong2 dv = __ldg((const longlong2*)ei + NEDGES / 2 + i);
        s0 = (int)sv.x; s1 = (int)sv.y; d0 = (int)dv.x; d1 = (int)dv.y;
    } else {
        int2 sv = __ldg((const int2*)ei + i);
        int2 dv = __ldg((const int2*)ei + NEDGES / 2 + i);
        s0 = sv.x; s1 = sv.y; d0 = dv.x; d1 = dv.y;
    }
    int p0 = atomicAdd(&g_cur[d0], 1);
    g_src[p0] = s0;
    int p1 = atomicAdd(&g_cur[d1], 1);
    g_src[p1] = s1;
}

// -------------------- gather1 (chunked): agg(x fp16) -> bf16 hi/lo + q ------
__global__ __launch_bounds__(256) void k_gather1(int nbase, int ncnt) {
    const int lane = threadIdx.x & 31;
    const int node = nbase + ((blockIdx.x * blockDim.x + threadIdx.x) >> 5);
    if (node >= nbase + ncnt || node >= NNODES) return;
    const float dv = g_dinv[node];
    const int e0 = g_off[node], e1 = g_off[node + 1];
    float4 acc = make_float4(0.f, 0.f, 0.f, 0.f);
    float q = 0.f;

    auto rowfma = [&](int s, float w) {
        uint2 hv = __ldg((const uint2*)(g_xh + (size_t)s * INDIM) + lane);
        __half2 p0 = *(__half2*)&hv.x;
        __half2 p1 = *(__half2*)&hv.y;
        float2 f0 = __half22float2(p0);
        float2 f1 = __half22float2(p1);
        acc.x += f0.x * w; acc.y += f0.y * w;
        acc.z += f1.x * w; acc.w += f1.y * w;
    };

    int e = e0;
    for (; e + 4 <= e1; e += 4) {
        int s0 = __ldg(&g_src[e]),     s1 = __ldg(&g_src[e + 1]);
        int s2 = __ldg(&g_src[e + 2]), s3 = __ldg(&g_src[e + 3]);
        float w0 = __ldg(&g_dinv[s0]) * dv, w1 = __ldg(&g_dinv[s1]) * dv;
        float w2 = __ldg(&g_dinv[s2]) * dv, w3 = __ldg(&g_dinv[s3]) * dv;
        q += (w0 + w1) + (w2 + w3);
        rowfma(s0, w0); rowfma(s1, w1); rowfma(s2, w2); rowfma(s3, w3);
    }
    for (; e < e1; e++) {
        int s0 = __ldg(&g_src[e]);
        float w0 = __ldg(&g_dinv[s0]) * dv;
        q += w0;
        rowfma(s0, w0);
    }
    {
        float w = dv * dv;
        q += w;
        rowfma(node, w);
    }
    float vals[4] = {acc.x, acc.y, acc.z, acc.w};
    uint32_t hp[2], lp[2];
#pragma unroll
    for (int p = 0; p < 2; p++) {
        __nv_bfloat16 h0 = __float2bfloat16_rn(vals[p * 2]);
        __nv_bfloat16 h1 = __float2bfloat16_rn(vals[p * 2 + 1]);
        __nv_bfloat16 l0 = __float2bfloat16_rn(vals[p * 2] - __bfloat162float(h0));
        __nv_bfloat16 l1 = __float2bfloat16_rn(vals[p * 2 + 1] - __bfloat162float(h1));
        hp[p] = (uint32_t)__bfloat16_as_ushort(h0) | ((uint32_t)__bfloat16_as_ushort(h1) << 16);
        lp[p] = (uint32_t)__bfloat16_as_ushort(l0) | ((uint32_t)__bfloat16_as_ushort(l1) << 16);
    }
    size_t base = (size_t)node * INDIM + lane * 4;
    *(uint2*)&g_aggx_hi[base] = make_uint2(hp[0], hp[1]);
    *(uint2*)&g_aggx_lo[base] = make_uint2(lp[0], lp[1]);
    if (lane == 0) g_q[node] = q;
}

// -------------------- double-buffered split-bf16 GEMM (row-chunked) ---------
template <int K, int NTOT, int BN, bool L1>
__global__ __launch_bounds__(256) void k_mma(
    const __nv_bfloat16* __restrict__ Ahi, const __nv_bfloat16* __restrict__ Alo,
    const __nv_bfloat16* __restrict__ Bhi, const __nv_bfloat16* __restrict__ Blo,
    const float* __restrict__ bias, const float* __restrict__ slope,
    __nv_bfloat16* __restrict__ OutHi, __nv_bfloat16* __restrict__ OutLo,
    __half* __restrict__ OutH, int rowbase, int M) {
    constexpr int BK = 32, SA = 40;
    constexpr int NSEG = K / BK;
    constexpr int TA = 128 * SA * 2;
    constexpr int TB = BN * SA * 2;
    constexpr int BUF = 2 * TA + 2 * TB;
    constexpr int NQ = BN / 32;

    extern __shared__ __align__(16) __nv_bfloat16 smem[];

    const int t = threadIdx.x;
    const int lane = t & 31, warp = t >> 5;
    const int wm0 = (warp >> 1) * 32;
    const int wn0 = (warp & 1) * (BN / 2);
    const int row0 = rowbase + blockIdx.y * 128;
    const int n0 = blockIdx.x * BN;

    auto load_seg = [&](int seg, int b) {
        const int k0 = seg * BK;
        const uint32_t sbase = smem_u32(smem) + (uint32_t)b * BUF;
#pragma unroll
        for (int tl = 0; tl < 2; tl++) {
            const __nv_bfloat16* G = tl ? Alo : Ahi;
            uint32_t tbase = sbase + tl * TA;
#pragma unroll
            for (int c = t; c < 512; c += 256) {
                int r = c >> 2, ch = c & 3;
                int gr = row0 + r;
                uint32_t ok = (gr < M) ? 16u : 0u;
                cp16(tbase + r * (SA * 2) + ch * 16,
                     G + (size_t)gr * K + k0 + ch * 8, ok);
            }
        }
#pragma unroll
        for (int tl = 0; tl < 2; tl++) {
            const __nv_bfloat16* G = tl ? Blo : Bhi;
            uint32_t tbase = sbase + 2 * TA + tl * TB;
#pragma unroll
            for (int c = t; c < BN * 4; c += 256) {
                int r = c >> 2, ch = c & 3;
                cp16(tbase + r * (SA * 2) + ch * 16,
                     G + (size_t)(n0 + r) * K + k0 + ch * 8, 16u);
            }
        }
        cp_commit();
    };

    float acc[2][2 * NQ][4] = {};

    load_seg(0, 0);
    for (int s = 0; s < NSEG; s++) {
        const int b = s & 1;
        if (s + 1 < NSEG) load_seg(s + 1, b ^ 1);
        if (s + 1 < NSEG) cp_wait<1>(); else cp_wait<0>();
        __syncthreads();

        const uint32_t sb = smem_u32(smem) + (uint32_t)b * BUF;
        const uint32_t aHi = sb, aLo = sb + TA;
        const uint32_t bHi = sb + 2 * TA, bLo = sb + 2 * TA + TB;

#pragma unroll
        for (int ph = 0; ph < 3; ph++) {
            const uint32_t at = (ph == 1) ? aLo : aHi;
            const uint32_t bt = (ph == 2) ? bLo : bHi;
#pragma unroll
            for (int kh = 0; kh < 2; kh++) {
                uint32_t af[2][4], bf[NQ][4];
#pragma unroll
                for (int mi = 0; mi < 2; mi++) {
                    uint32_t addr = at +
                        ((wm0 + mi * 16 + (lane & 15)) * SA + kh * 16 + (lane >> 4) * 8) * 2;
                    ldsm_x4(af[mi], addr);
                }
#pragma unroll
                for (int nq = 0; nq < NQ; nq++) {
                    uint32_t addr = bt +
                        ((wn0 + nq * 16 + (lane & 7) + ((lane >> 4) & 1) * 8) * SA +
                         kh * 16 + ((lane >> 3) & 1) * 8) * 2;
                    ldsm_x4(bf[nq], addr);
                }
#pragma unroll
                for (int mi = 0; mi < 2; mi++)
#pragma unroll
                    for (int nq = 0; nq < NQ; nq++) {
                        mma_bf16(acc[mi][nq * 2],     af[mi], bf[nq][0], bf[nq][1]);
                        mma_bf16(acc[mi][nq * 2 + 1], af[mi], bf[nq][2], bf[nq][3]);
                    }
            }
        }
        __syncthreads();
    }

    float qv[2][2];
    if (L1) {
#pragma unroll
        for (int mi = 0; mi < 2; mi++) {
            int r0 = row0 + wm0 + mi * 16 + (lane >> 2);
            qv[mi][0] = (r0 < M) ? __ldg(&g_q[r0]) : 0.f;
            qv[mi][1] = (r0 + 8 < M) ? __ldg(&g_q[r0 + 8]) : 0.f;
        }
    }
#pragma unroll
    for (int mi = 0; mi < 2; mi++) {
        int r0 = row0 + wm0 + mi * 16 + (lane >> 2);
#pragma unroll
        for (int nt = 0; nt < 2 * NQ; nt++) {
            int c0 = n0 + wn0 + nt * 8 + (lane & 3) * 2;
            if (L1) {
                float cc0 = __ldg(&g_c1[c0]),   cc1 = __ldg(&g_c1[c0 + 1]);
                float bb0 = __ldg(&bias[c0]),   bb1 = __ldg(&bias[c0 + 1]);
                float ss0 = __ldg(&slope[c0]),  ss1 = __ldg(&slope[c0 + 1]);
#pragma unroll
                for (int h = 0; h < 2; h++) {
                    int r = r0 + h * 8;
                    if (r >= M) continue;
                    float v0 = acc[mi][nt][h * 2]     + qv[mi][h] * cc0 + bb0;
                    float v1 = acc[mi][nt][h * 2 + 1] + qv[mi][h] * cc1 + bb1;
                    v0 = v0 >= 0.f ? v0 : ss0 * v0;
                    v1 = v1 >= 0.f ? v1 : ss1 * v1;
                    __nv_bfloat16 h0 = __float2bfloat16_rn(v0);
                    __nv_bfloat16 h1 = __float2bfloat16_rn(v1);
                    __nv_bfloat16 l0 = __float2bfloat16_rn(v0 - __bfloat162float(h0));
                    __nv_bfloat16 l1 = __float2bfloat16_rn(v1 - __bfloat162float(h1));
                    size_t o = (size_t)r * NTOT + c0;
                    *(uint32_t*)(OutHi + o) = (uint32_t)__bfloat16_as_ushort(h0) |
                                              ((uint32_t)__bfloat16_as_ushort(h1) << 16);
                    *(uint32_t*)(OutLo + o) = (uint32_t)__bfloat16_as_ushort(l0) |
                                              ((uint32_t)__bfloat16_as_ushort(l1) << 16);
                }
            } else {
#pragma unroll
                for (int h = 0; h < 2; h++) {
                    int r = r0 + h * 8;
                    if (r >= M) continue;
                    __half2 hh = __floats2half2_rn(acc[mi][nt][h * 2],
                                                   acc[mi][nt][h * 2 + 1]);
                    *(uint32_t*)(OutH + (size_t)r * NTOT + c0) = *(uint32_t*)&hh;
                }
            }
        }
    }
}

// -------------------- gather2: fp16 h2 rows, fused bias+prelu ---------------
__global__ __launch_bounds__(256) void k_gather2(const float* __restrict__ bias,
                                                 const float* __restrict__ slope,
                                                 float* __restrict__ out) {
    const int lane = threadIdx.x & 31;
    const int node = (blockIdx.x * blockDim.x + threadIdx.x) >> 5;
    if (node >= NNODES) return;
    const float dv = g_dinv[node];
    const int e0 = g_off[node], e1 = g_off[node + 1];
    float4 acc = make_float4(0.f, 0.f, 0.f, 0.f);

    auto rowfma = [&](int s, float w) {
        uint2 hv = __ldg((const uint2*)(g_h2 + (size_t)s * OUTD) + lane);
        __half2 p0 = *(__half2*)&hv.x;
        __half2 p1 = *(__half2*)&hv.y;
        float2 f0 = __half22float2(p0);
        float2 f1 = __half22float2(p1);
        acc.x += f0.x * w; acc.y += f0.y * w;
        acc.z += f1.x * w; acc.w += f1.y * w;
    };

    int e = e0;
    for (; e + 4 <= e1; e += 4) {
        int s0 = __ldg(&g_src[e]),     s1 = __ldg(&g_src[e + 1]);
        int s2 = __ldg(&g_src[e + 2]), s3 = __ldg(&g_src[e + 3]);
        float w0 = __ldg(&g_dinv[s0]) * dv, w1 = __ldg(&g_dinv[s1]) * dv;
        float w2 = __ldg(&g_dinv[s2]) * dv, w3 = __ldg(&g_dinv[s3]) * dv;
        rowfma(s0, w0); rowfma(s1, w1); rowfma(s2, w2); rowfma(s3, w3);
    }
    for (; e < e1; e++) {
        int s0 = __ldg(&g_src[e]);
        float w0 = __ldg(&g_dinv[s0]) * dv;
        rowfma(s0, w0);
    }
    rowfma(node, dv * dv);

    float4 B = *(const float4*)&bias[lane * 4];
    float4 S = *(const float4*)&slope[lane * 4];
    float r0 = acc.x + B.x, r1 = acc.y + B.y, r2 = acc.z + B.z, r3 = acc.w + B.w;
    float4 o;
    o.x = r0 >= 0.f ? r0 : S.x * r0;
    o.y = r1 >= 0.f ? r1 : S.y * r1;
    o.z = r2 >= 0.f ? r2 : S.z * r2;
    o.w = r3 >= 0.f ? r3 : S.w * r3;
    *(float4*)&out[(size_t)node * OUTD + lane * 4] = o;
}

// -------------------- launch ------------------------------------------------
extern "C" void kernel_launch(void* const* d_in, const int* in_sizes, int n_in,
                              void* d_out, int out_size) {
    const float* x  = (const float*)d_in[0];
    const void*  ei = d_in[1];
    const float* idv = (const float*)d_in[2];
    const float* W1 = (const float*)d_in[3];
    const float* b1 = (const float*)d_in[4];
    const float* a1 = (const float*)d_in[5];
    const float* W2 = (const float*)d_in[6];
    const float* b2 = (const float*)d_in[7];
    const float* a2 = (const float*)d_in[8];
    float* out = (float*)d_out;

    __nv_bfloat16 *d_axh, *d_axl, *d_h1h, *d_h1l, *d_w1h, *d_w1l, *d_w2h, *d_w2l;
    __half *d_h2;
    cudaGetSymbolAddress((void**)&d_axh, g_aggx_hi);
    cudaGetSymbolAddress((void**)&d_axl, g_aggx_lo);
    cudaGetSymbolAddress((void**)&d_h1h, g_h1_hi);
    cudaGetSymbolAddress((void**)&d_h1l, g_h1_lo);
    cudaGetSymbolAddress((void**)&d_w1h, g_wt1_hi);
    cudaGetSymbolAddress((void**)&d_w1l, g_wt1_lo);
    cudaGetSymbolAddress((void**)&d_w2h, g_wt2_hi);
    cudaGetSymbolAddress((void**)&d_w2l, g_wt2_lo);
    cudaGetSymbolAddress((void**)&d_h2, g_h2);

    const int T = 256;
    constexpr int SMEM1 = 2 * (2 * 128 + 2 * 128) * 40 * 2;   // 81920 B
    constexpr int SMEM2 = 2 * (2 * 128 + 2 * 64) * 40 * 2;    // 61440 B
    constexpr int C0 = CHUNK0, C1 = NNODES - CHUNK0;
    constexpr int T0 = C0 / 128, T1 = (C1 + 127) / 128;

    static cudaStream_t s1 = nullptr;
    static cudaEvent_t evScan, evPrep, evG0, evG1, evMma;
    if (!s1) {
        cudaStreamCreate(&s1);
        cudaEventCreateWithFlags(&evScan, cudaEventDisableTiming);
        cudaEventCreateWithFlags(&evPrep, cudaEventDisableTiming);
        cudaEventCreateWithFlags(&evG0,   cudaEventDisableTiming);
        cudaEventCreateWithFlags(&evG1,   cudaEventDisableTiming);
        cudaEventCreateWithFlags(&evMma,  cudaEventDisableTiming);
        cudaFuncSetAttribute(k_mma<INDIM, HID, 128, true>,
                             cudaFuncAttributeMaxDynamicSharedMemorySize, SMEM1);
        cudaFuncSetAttribute(k_mma<HID, OUTD, 64, false>,
                             cudaFuncAttributeMaxDynamicSharedMemorySize, SMEM2);
    }

    // serial edge chain prefix (scan runs uncontended)
    k_init<<<(NNODES + T - 1) / T, T>>>((const long long*)ei);
    k_deg<<<(NEDGES / 2 + T - 1) / T, T>>>(ei);
    k_scan<<<1, 1024>>>();
    cudaEventRecord(evScan, 0);

    // fork: dense prep on s1 overlaps ONLY k_csr
    cudaStreamWaitEvent(s1, evScan, 0);
    {
        constexpr int TOT = NNODES * INDIM / 4 + HID * INDIM + OUTD * HID + HID;
        k_prepd<<<(TOT + T - 1) / T, T, 0, s1>>>(x, W1, W2, idv);
    }
    k_csr<<<(NEDGES / 2 + T - 1) / T, T>>>(ei);

    // join dense prep before gather1 (needs g_xh)
    cudaEventRecord(evPrep, s1);
    cudaStreamWaitEvent(0, evPrep, 0);

    // pipeline: gather1 chunk0 -> (gather1 chunk1 || GEMM chunk0) -> GEMM chunk1
    k_gather1<<<(C0 * 32 + T - 1) / T, T>>>(0, C0);
    cudaEventRecord(evG0, 0);
    k_gather1<<<(C1 * 32 + T - 1) / T, T>>>(C0, C1);
    cudaEventRecord(evG1, 0);

    cudaStreamWaitEvent(s1, evG0, 0);
    {
        dim3 g1(HID / 128, T0);
        k_mma<INDIM, HID, 128, true><<<g1, 256, SMEM1, s1>>>(
            d_axh, d_axl, d_w1h, d_w1l, b1, a1, d_h1h, d_h1l, nullptr, 0, NNODES);
        dim3 g2(OUTD / 64, T0);
        k_mma<HID, OUTD, 64, false><<<g2, 256, SMEM2, s1>>>(
            d_h1h, d_h1l, d_w2h, d_w2l, nullptr, nullptr, nullptr, nullptr,
            d_h2, 0, NNODES);
    }
    cudaStreamWaitEvent(s1, evG1, 0);
    {
        dim3 g1(HID / 128, T1);
        k_mma<INDIM, HID, 128, true><<<g1, 256, SMEM1, s1>>>(
            d_axh, d_axl, d_w1h, d_w1l, b1, a1, d_h1h, d_h1l, nullptr, C0, NNODES);
        dim3 g2(OUTD / 64, T1);
        k_mma<HID, OUTD, 64, false><<<g2, 256, SMEM2, s1>>>(
            d_h1h, d_h1l, d_w2h, d_w2l, nullptr, nullptr, nullptr, nullptr,
            d_h2, C0, NNODES);
    }
    cudaEventRecord(evMma, s1);
    cudaStreamWaitEvent(0, evMma, 0);

    k_gather2<<<(NNODES * 32 + T - 1) / T, T>>>(b2, a2, out);
}

// round 13
// speedup vs baseline: 1.0467x; 1.0467x over previous
#include <cuda_runtime.h>
#include <cuda_bf16.h>
#include <cuda_fp16.h>
#include <cstdint>

// ---------------------------------------------------------------------------
// 2-layer GCN. R13 = R10 serial pipeline (unfragmented grids) + ONE fork:
//   s1: prepd (x->fp16, weight split, c1) overlaps s0: init+deg (+scan tail).
//   s0: init -> deg -> scan -> csr -> [join prepd] -> gather1 -> GEMM1 -> GEMM2 -> gather2
// ---------------------------------------------------------------------------

static constexpr int NNODES = 50000;
static constexpr int NEDGES = 800000;
static constexpr int INDIM  = 128;
static constexpr int ADDDIM = 8;
static constexpr int HID    = 256;
static constexpr int OUTD   = 128;

// -------------------- device scratch ----------------------------------------
__device__ __align__(16) __half g_xh[(size_t)NNODES * INDIM];
__device__ __align__(16) __nv_bfloat16 g_aggx_hi[(size_t)NNODES * INDIM];
__device__ __align__(16) __nv_bfloat16 g_aggx_lo[(size_t)NNODES * INDIM];
__device__ __align__(16) __nv_bfloat16 g_h1_hi[(size_t)NNODES * HID];
__device__ __align__(16) __nv_bfloat16 g_h1_lo[(size_t)NNODES * HID];
__device__ __align__(16) __half g_h2[(size_t)NNODES * OUTD];
__device__ float g_q[NNODES];
__device__ float g_dinv[NNODES];
__device__ int   g_deg[NNODES];
__device__ int   g_off[NNODES + 1];
__device__ int   g_cur[NNODES];
__device__ int   g_src[NEDGES];
__device__ float g_c1[HID];
__device__ __align__(16) __nv_bfloat16 g_wt1_hi[HID * INDIM], g_wt1_lo[HID * INDIM];
__device__ __align__(16) __nv_bfloat16 g_wt2_hi[OUTD * HID],  g_wt2_lo[OUTD * HID];
__device__ int g_is64;

// -------------------- asm helpers -------------------------------------------
__device__ __forceinline__ uint32_t smem_u32(const void* p) {
    return (uint32_t)__cvta_generic_to_shared(p);
}
__device__ __forceinline__ void ldsm_x4(uint32_t r[4], uint32_t addr) {
    asm volatile("ldmatrix.sync.aligned.m8n8.x4.shared.b16 {%0,%1,%2,%3}, [%4];"
                 : "=r"(r[0]), "=r"(r[1]), "=r"(r[2]), "=r"(r[3]) : "r"(addr));
}
__device__ __forceinline__ void mma_bf16(float* c, const uint32_t* a,
                                         uint32_t b0, uint32_t b1) {
    asm volatile(
        "mma.sync.aligned.m16n8k16.row.col.f32.bf16.bf16.f32 "
        "{%0,%1,%2,%3}, {%4,%5,%6,%7}, {%8,%9}, {%0,%1,%2,%3};"
        : "+f"(c[0]), "+f"(c[1]), "+f"(c[2]), "+f"(c[3])
        : "r"(a[0]), "r"(a[1]), "r"(a[2]), "r"(a[3]), "r"(b0), "r"(b1));
}
__device__ __forceinline__ void cp16(uint32_t dst, const void* src, uint32_t sz) {
    asm volatile("cp.async.cg.shared.global [%0], [%1], 16, %2;"
                 :: "r"(dst), "l"(src), "r"(sz) : "memory");
}
__device__ __forceinline__ void cp_commit() {
    asm volatile("cp.async.commit_group;" ::: "memory");
}
template <int N>
__device__ __forceinline__ void cp_wait() {
    asm volatile("cp.async.wait_group %0;" :: "n"(N) : "memory");
}

// -------------------- prep kernels ------------------------------------------
__global__ void k_init(const long long* __restrict__ ei) {
    int i = blockIdx.x * blockDim.x + threadIdx.x;
    if (i < NNODES) g_deg[i] = 0;
    if (blockIdx.x == 0 && threadIdx.x < 32) {
        bool bad = false;
        for (int j = threadIdx.x; j < 512; j += 32) {
            long long v = ei[j];
            if (v < 0 || v >= NNODES) bad = true;
        }
        unsigned m = __ballot_sync(0xFFFFFFFFu, bad);
        if (threadIdx.x == 0) g_is64 = (m == 0u) ? 1 : 0;
    }
}
// dense prep: x->fp16, weight split+transpose, c1 (depends only on inputs)
__global__ void k_prepd(const float* __restrict__ x,
                        const float* __restrict__ W1, const float* __restrict__ W2,
                        const float* __restrict__ idv) {
    constexpr int XT = NNODES * INDIM / 4;
    constexpr int N1 = HID * INDIM;
    constexpr int N2 = OUTD * HID;
    int idx = blockIdx.x * blockDim.x + threadIdx.x;
    if (idx < XT) {
        float4 v = __ldg((const float4*)x + idx);
        __half2 p0 = __floats2half2_rn(v.x, v.y);
        __half2 p1 = __floats2half2_rn(v.z, v.w);
        uint2 o;
        o.x = *(uint32_t*)&p0;
        o.y = *(uint32_t*)&p1;
        *((uint2*)g_xh + idx) = o;
    } else if (idx < XT + N1) {
        int j = idx - XT;
        int o = j / INDIM, i = j % INDIM;
        float v = W1[(size_t)i * HID + o];
        __nv_bfloat16 h = __float2bfloat16_rn(v);
        g_wt1_hi[j] = h;
        g_wt1_lo[j] = __float2bfloat16_rn(v - __bfloat162float(h));
    } else if (idx < XT + N1 + N2) {
        int j = idx - XT - N1;
        int o = j / HID, i = j % HID;
        float v = W2[(size_t)i * OUTD + o];
        __nv_bfloat16 h = __float2bfloat16_rn(v);
        g_wt2_hi[j] = h;
        g_wt2_lo[j] = __float2bfloat16_rn(v - __bfloat162float(h));
    } else if (idx < XT + N1 + N2 + HID) {
        int j = idx - XT - N1 - N2;
        float s = 0.f;
#pragma unroll
        for (int t = 0; t < ADDDIM; t++) s += idv[t] * W1[(size_t)(INDIM + t) * HID + j];
        g_c1[j] = s;
    }
}

__global__ void k_deg(const void* __restrict__ ei) {
    int i = blockIdx.x * blockDim.x + threadIdx.x;
    if (i >= NEDGES / 2) return;
    int d0, d1;
    if (g_is64) {
        longlong2 v = __ldg((const longlong2*)ei + NEDGES / 2 + i);
        d0 = (int)v.x; d1 = (int)v.y;
    } else {
        int2 v = __ldg((const int2*)ei + NEDGES / 2 + i);
        d0 = v.x; d1 = v.y;
    }
    atomicAdd(&g_deg[d0], 1);
    atomicAdd(&g_deg[d1], 1);
}
__global__ void k_scan() {
    __shared__ int warpsum[32];
    __shared__ int chunk_total;
    const int t = threadIdx.x;               // 1024
    const int lane = t & 31, wid = t >> 5;
    int run = 0;
    for (int base = 0; base < NNODES; base += 2048) {
        int i0 = base + t * 2, i1 = i0 + 1;
        int v0 = (i0 < NNODES) ? g_deg[i0] : 0;
        int v1 = (i1 < NNODES) ? g_deg[i1] : 0;
        if (i0 < NNODES) g_dinv[i0] = rsqrtf((float)(v0 + 1));
        if (i1 < NNODES) g_dinv[i1] = rsqrtf((float)(v1 + 1));
        int v = v0 + v1;
        int x = v;
#pragma unroll
        for (int o = 1; o < 32; o <<= 1) {
            int y = __shfl_up_sync(0xFFFFFFFFu, x, o);
            if (lane >= o) x += y;
        }
        if (lane == 31) warpsum[wid] = x;
        __syncthreads();
        if (wid == 0) {
            int w = warpsum[lane];
#pragma unroll
            for (int o = 1; o < 32; o <<= 1) {
                int y = __shfl_up_sync(0xFFFFFFFFu, w, o);
                if (lane >= o) w += y;
            }
            warpsum[lane] = w;
            if (lane == 31) chunk_total = w;
        }
        __syncthreads();
        int excl = run + (wid ? warpsum[wid - 1] : 0) + x - v;
        if (i0 < NNODES) { g_off[i0] = excl; g_cur[i0] = excl; }
        if (i1 < NNODES) { g_off[i1] = excl + v0; g_cur[i1] = excl + v0; }
        run += chunk_total;
        __syncthreads();
    }
    if (t == 0) g_off[NNODES] = run;
}
__global__ void k_csr(const void* __restrict__ ei) {
    int i = blockIdx.x * blockDim.x + threadIdx.x;
    if (i >= NEDGES / 2) return;
    int s0, s1, d0, d1;
    if (g_is64) {
        longlong2 sv = __ldg((const longlong2*)ei + i);
        longlong2 dv = __ldg((const longlong2*)ei + NEDGES / 2 + i);
        s0 = (int)sv.x; s1 = (int)sv.y; d0 = (int)dv.x; d1 = (int)dv.y;
    } else {
        int2 sv = __ldg((const int2*)ei + i);
        int2 dv = __ldg((const int2*)ei + NEDGES / 2 + i);
        s0 = sv.x; s1 = sv.y; d0 = dv.x; d1 = dv.y;
    }
    int p0 = atomicAdd(&g_cur[d0], 1);
    g_src[p0] = s0;
    int p1 = atomicAdd(&g_cur[d1], 1);
    g_src[p1] = s1;
}

// -------------------- gather1: agg(x fp16) -> bf16 hi/lo + q ----------------
__global__ __launch_bounds__(256) void k_gather1() {
    const int lane = threadIdx.x & 31;
    const int node = (blockIdx.x * blockDim.x + threadIdx.x) >> 5;
    if (node >= NNODES) return;
    const float dv = g_dinv[node];
    const int e0 = g_off[node], e1 = g_off[node + 1];
    float4 acc = make_float4(0.f, 0.f, 0.f, 0.f);
    float q = 0.f;

    auto rowfma = [&](int s, float w) {
        uint2 hv = __ldg((const uint2*)(g_xh + (size_t)s * INDIM) + lane);
        __half2 p0 = *(__half2*)&hv.x;
        __half2 p1 = *(__half2*)&hv.y;
        float2 f0 = __half22float2(p0);
        float2 f1 = __half22float2(p1);
        acc.x += f0.x * w; acc.y += f0.y * w;
        acc.z += f1.x * w; acc.w += f1.y * w;
    };

    int e = e0;
    for (; e + 4 <= e1; e += 4) {
        int s0 = __ldg(&g_src[e]),     s1 = __ldg(&g_src[e + 1]);
        int s2 = __ldg(&g_src[e + 2]), s3 = __ldg(&g_src[e + 3]);
        float w0 = __ldg(&g_dinv[s0]) * dv, w1 = __ldg(&g_dinv[s1]) * dv;
        float w2 = __ldg(&g_dinv[s2]) * dv, w3 = __ldg(&g_dinv[s3]) * dv;
        q += (w0 + w1) + (w2 + w3);
        rowfma(s0, w0); rowfma(s1, w1); rowfma(s2, w2); rowfma(s3, w3);
    }
    for (; e < e1; e++) {
        int s0 = __ldg(&g_src[e]);
        float w0 = __ldg(&g_dinv[s0]) * dv;
        q += w0;
        rowfma(s0, w0);
    }
    {
        float w = dv * dv;
        q += w;
        rowfma(node, w);
    }
    float vals[4] = {acc.x, acc.y, acc.z, acc.w};
    uint32_t hp[2], lp[2];
#pragma unroll
    for (int p = 0; p < 2; p++) {
        __nv_bfloat16 h0 = __float2bfloat16_rn(vals[p * 2]);
        __nv_bfloat16 h1 = __float2bfloat16_rn(vals[p * 2 + 1]);
        __nv_bfloat16 l0 = __float2bfloat16_rn(vals[p * 2] - __bfloat162float(h0));
        __nv_bfloat16 l1 = __float2bfloat16_rn(vals[p * 2 + 1] - __bfloat162float(h1));
        hp[p] = (uint32_t)__bfloat16_as_ushort(h0) | ((uint32_t)__bfloat16_as_ushort(h1) << 16);
        lp[p] = (uint32_t)__bfloat16_as_ushort(l0) | ((uint32_t)__bfloat16_as_ushort(l1) << 16);
    }
    size_t base = (size_t)node * INDIM + lane * 4;
    *(uint2*)&g_aggx_hi[base] = make_uint2(hp[0], hp[1]);
    *(uint2*)&g_aggx_lo[base] = make_uint2(lp[0], lp[1]);
    if (lane == 0) g_q[node] = q;
}

// -------------------- double-buffered split-bf16 GEMM -----------------------
template <int K, int NTOT, int BN, bool L1>
__global__ __launch_bounds__(256) void k_mma(
    const __nv_bfloat16* __restrict__ Ahi, const __nv_bfloat16* __restrict__ Alo,
    const __nv_bfloat16* __restrict__ Bhi, const __nv_bfloat16* __restrict__ Blo,
    const float* __restrict__ bias, const float* __restrict__ slope,
    __nv_bfloat16* __restrict__ OutHi, __nv_bfloat16* __restrict__ OutLo,
    __half* __restrict__ OutH, int M) {
    constexpr int BK = 32, SA = 40;
    constexpr int NSEG = K / BK;
    constexpr int TA = 128 * SA * 2;
    constexpr int TB = BN * SA * 2;
    constexpr int BUF = 2 * TA + 2 * TB;
    constexpr int NQ = BN / 32;

    extern __shared__ __align__(16) __nv_bfloat16 smem[];

    const int t = threadIdx.x;
    const int lane = t & 31, warp = t >> 5;
    const int wm0 = (warp >> 1) * 32;
    const int wn0 = (warp & 1) * (BN / 2);
    const int row0 = blockIdx.y * 128;
    const int n0 = blockIdx.x * BN;

    auto load_seg = [&](int seg, int b) {
        const int k0 = seg * BK;
        const uint32_t sbase = smem_u32(smem) + (uint32_t)b * BUF;
#pragma unroll
        for (int tl = 0; tl < 2; tl++) {
            const __nv_bfloat16* G = tl ? Alo : Ahi;
            uint32_t tbase = sbase + tl * TA;
#pragma unroll
            for (int c = t; c < 512; c += 256) {
                int r = c >> 2, ch = c & 3;
                int gr = row0 + r;
                uint32_t ok = (gr < M) ? 16u : 0u;
                cp16(tbase + r * (SA * 2) + ch * 16,
                     G + (size_t)gr * K + k0 + ch * 8, ok);
            }
        }
#pragma unroll
        for (int tl = 0; tl < 2; tl++) {
            const __nv_bfloat16* G = tl ? Blo : Bhi;
            uint32_t tbase = sbase + 2 * TA + tl * TB;
#pragma unroll
            for (int c = t; c < BN * 4; c += 256) {
                int r = c >> 2, ch = c & 3;
                cp16(tbase + r * (SA * 2) + ch * 16,
                     G + (size_t)(n0 + r) * K + k0 + ch * 8, 16u);
            }
        }
        cp_commit();
    };

    float acc[2][2 * NQ][4] = {};

    load_seg(0, 0);
    for (int s = 0; s < NSEG; s++) {
        const int b = s & 1;
        if (s + 1 < NSEG) load_seg(s + 1, b ^ 1);
        if (s + 1 < NSEG) cp_wait<1>(); else cp_wait<0>();
        __syncthreads();

        const uint32_t sb = smem_u32(smem) + (uint32_t)b * BUF;
        const uint32_t aHi = sb, aLo = sb + TA;
        const uint32_t bHi = sb + 2 * TA, bLo = sb + 2 * TA + TB;

#pragma unroll
        for (int ph = 0; ph < 3; ph++) {
            const uint32_t at = (ph == 1) ? aLo : aHi;
            const uint32_t bt = (ph == 2) ? bLo : bHi;
#pragma unroll
            for (int kh = 0; kh < 2; kh++) {
                uint32_t af[2][4], bf[NQ][4];
#pragma unroll
                for (int mi = 0; mi < 2; mi++) {
                    uint32_t addr = at +
                        ((wm0 + mi * 16 + (lane & 15)) * SA + kh * 16 + (lane >> 4) * 8) * 2;
                    ldsm_x4(af[mi], addr);
                }
#pragma unroll
                for (int nq = 0; nq < NQ; nq++) {
                    uint32_t addr = bt +
                        ((wn0 + nq * 16 + (lane & 7) + ((lane >> 4) & 1) * 8) * SA +
                         kh * 16 + ((lane >> 3) & 1) * 8) * 2;
                    ldsm_x4(bf[nq], addr);
                }
#pragma unroll
                for (int mi = 0; mi < 2; mi++)
#pragma unroll
                    for (int nq = 0; nq < NQ; nq++) {
                        mma_bf16(acc[mi][nq * 2],     af[mi], bf[nq][0], bf[nq][1]);
                        mma_bf16(acc[mi][nq * 2 + 1], af[mi], bf[nq][2], bf[nq][3]);
                    }
            }
        }
        __syncthreads();
    }

    float qv[2][2];
    if (L1) {
#pragma unroll
        for (int mi = 0; mi < 2; mi++) {
            int r0 = row0 + wm0 + mi * 16 + (lane >> 2);
            qv[mi][0] = (r0 < M) ? __ldg(&g_q[r0]) : 0.f;
            qv[mi][1] = (r0 + 8 < M) ? __ldg(&g_q[r0 + 8]) : 0.f;
        }
    }
#pragma unroll
    for (int mi = 0; mi < 2; mi++) {
        int r0 = row0 + wm0 + mi * 16 + (lane >> 2);
#pragma unroll
        for (int nt = 0; nt < 2 * NQ; nt++) {
            int c0 = n0 + wn0 + nt * 8 + (lane & 3) * 2;
            if (L1) {
                float cc0 = __ldg(&g_c1[c0]),   cc1 = __ldg(&g_c1[c0 + 1]);
                float bb0 = __ldg(&bias[c0]),   bb1 = __ldg(&bias[c0 + 1]);
                float ss0 = __ldg(&slope[c0]),  ss1 = __ldg(&slope[c0 + 1]);
#pragma unroll
                for (int h = 0; h < 2; h++) {
                    int r = r0 + h * 8;
                    if (r >= M) continue;
                    float v0 = acc[mi][nt][h * 2]     + qv[mi][h] * cc0 + bb0;
                    float v1 = acc[mi][nt][h * 2 + 1] + qv[mi][h] * cc1 + bb1;
                    v0 = v0 >= 0.f ? v0 : ss0 * v0;
                    v1 = v1 >= 0.f ? v1 : ss1 * v1;
                    __nv_bfloat16 h0 = __float2bfloat16_rn(v0);
                    __nv_bfloat16 h1 = __float2bfloat16_rn(v1);
                    __nv_bfloat16 l0 = __float2bfloat16_rn(v0 - __bfloat162float(h0));
                    __nv_bfloat16 l1 = __float2bfloat16_rn(v1 - __bfloat162float(h1));
                    size_t o = (size_t)r * NTOT + c0;
                    *(uint32_t*)(OutHi + o) = (uint32_t)__bfloat16_as_ushort(h0) |
                                              ((uint32_t)__bfloat16_as_ushort(h1) << 16);
                    *(uint32_t*)(OutLo + o) = (uint32_t)__bfloat16_as_ushort(l0) |
                                              ((uint32_t)__bfloat16_as_ushort(l1) << 16);
                }
            } else {
#pragma unroll
                for (int h = 0; h < 2; h++) {
                    int r = r0 + h * 8;
                    if (r >= M) continue;
                    __half2 hh = __floats2half2_rn(acc[mi][nt][h * 2],
                                                   acc[mi][nt][h * 2 + 1]);
                    *(uint32_t*)(OutH + (size_t)r * NTOT + c0) = *(uint32_t*)&hh;
                }
            }
        }
    }
}

// -------------------- gather2: fp16 h2 rows, fused bias+prelu ---------------
__global__ __launch_bounds__(256) void k_gather2(const float* __restrict__ bias,
                                                 const float* __restrict__ slope,
                                                 float* __restrict__ out) {
    const int lane = threadIdx.x & 31;
    const int node = (blockIdx.x * blockDim.x + threadIdx.x) >> 5;
    if (node >= NNODES) return;
    const float dv = g_dinv[node];
    const int e0 = g_off[node], e1 = g_off[node + 1];
    float4 acc = make_float4(0.f, 0.f, 0.f, 0.f);

    auto rowfma = [&](int s, float w) {
        uint2 hv = __ldg((const uint2*)(g_h2 + (size_t)s * OUTD) + lane);
        __half2 p0 = *(__half2*)&hv.x;
        __half2 p1 = *(__half2*)&hv.y;
        float2 f0 = __half22float2(p0);
        float2 f1 = __half22float2(p1);
        acc.x += f0.x * w; acc.y += f0.y * w;
        acc.z += f1.x * w; acc.w += f1.y * w;
    };

    int e = e0;
    for (; e + 4 <= e1; e += 4) {
        int s0 = __ldg(&g_src[e]),     s1 = __ldg(&g_src[e + 1]);
        int s2 = __ldg(&g_src[e + 2]), s3 = __ldg(&g_src[e + 3]);
        float w0 = __ldg(&g_dinv[s0]) * dv, w1 = __ldg(&g_dinv[s1]) * dv;
        float w2 = __ldg(&g_dinv[s2]) * dv, w3 = __ldg(&g_dinv[s3]) * dv;
        rowfma(s0, w0); rowfma(s1, w1); rowfma(s2, w2); rowfma(s3, w3);
    }
    for (; e < e1; e++) {
        int s0 = __ldg(&g_src[e]);
        float w0 = __ldg(&g_dinv[s0]) * dv;
        rowfma(s0, w0);
    }
    rowfma(node, dv * dv);

    float4 B = *(const float4*)&bias[lane * 4];
    float4 S = *(const float4*)&slope[lane * 4];
    float r0 = acc.x + B.x, r1 = acc.y + B.y, r2 = acc.z + B.z, r3 = acc.w + B.w;
    float4 o;
    o.x = r0 >= 0.f ? r0 : S.x * r0;
    o.y = r1 >= 0.f ? r1 : S.y * r1;
    o.z = r2 >= 0.f ? r2 : S.z * r2;
    o.w = r3 >= 0.f ? r3 : S.w * r3;
    *(float4*)&out[(size_t)node * OUTD + lane * 4] = o;
}

// -------------------- launch ------------------------------------------------
extern "C" void kernel_launch(void* const* d_in, const int* in_sizes, int n_in,
                              void* d_out, int out_size) {
    const float* x  = (const float*)d_in[0];
    const void*  ei = d_in[1];
    const float* idv = (const float*)d_in[2];
    const float* W1 = (const float*)d_in[3];
    const float* b1 = (const float*)d_in[4];
    const float* a1 = (const float*)d_in[5];
    const float* W2 = (const float*)d_in[6];
    const float* b2 = (const float*)d_in[7];
    const float* a2 = (const float*)d_in[8];
    float* out = (float*)d_out;

    __nv_bfloat16 *d_axh, *d_axl, *d_h1h, *d_h1l, *d_w1h, *d_w1l, *d_w2h, *d_w2l;
    __half *d_h2;
    cudaGetSymbolAddress((void**)&d_axh, g_aggx_hi);
    cudaGetSymbolAddress((void**)&d_axl, g_aggx_lo);
    cudaGetSymbolAddress((void**)&d_h1h, g_h1_hi);
    cudaGetSymbolAddress((void**)&d_h1l, g_h1_lo);
    cudaGetSymbolAddress((void**)&d_w1h, g_wt1_hi);
    cudaGetSymbolAddress((void**)&d_w1l, g_wt1_lo);
    cudaGetSymbolAddress((void**)&d_w2h, g_wt2_hi);
    cudaGetSymbolAddress((void**)&d_w2l, g_wt2_lo);
    cudaGetSymbolAddress((void**)&d_h2, g_h2);

    const int T = 256;
    constexpr int SMEM1 = 2 * (2 * 128 + 2 * 128) * 40 * 2;   // 81920 B
    constexpr int SMEM2 = 2 * (2 * 128 + 2 * 64) * 40 * 2;    // 61440 B

    static cudaStream_t s1 = nullptr;
    static cudaEvent_t evFork, evPrep;
    if (!s1) {
        cudaStreamCreate(&s1);
        cudaEventCreateWithFlags(&evFork, cudaEventDisableTiming);
        cudaEventCreateWithFlags(&evPrep, cudaEventDisableTiming);
        cudaFuncSetAttribute(k_mma<INDIM, HID, 128, true>,
                             cudaFuncAttributeMaxDynamicSharedMemorySize, SMEM1);
        cudaFuncSetAttribute(k_mma<HID, OUTD, 64, false>,
                             cudaFuncAttributeMaxDynamicSharedMemorySize, SMEM2);
    }

    // fork at start: prepd on s1 overlaps init+deg (done before scan starts)
    cudaEventRecord(evFork, 0);
    cudaStreamWaitEvent(s1, evFork, 0);
    {
        constexpr int TOT = NNODES * INDIM / 4 + HID * INDIM + OUTD * HID + HID;
        k_prepd<<<(TOT + T - 1) / T, T, 0, s1>>>(x, W1, W2, idv);
    }
    cudaEventRecord(evPrep, s1);

    // serial edge chain on stream 0 (unfragmented)
    k_init<<<(NNODES + T - 1) / T, T>>>((const long long*)ei);
    k_deg<<<(NEDGES / 2 + T - 1) / T, T>>>(ei);
    k_scan<<<1, 1024>>>();
    k_csr<<<(NEDGES / 2 + T - 1) / T, T>>>(ei);

    // join prepd before gather1 (needs g_xh)
    cudaStreamWaitEvent(0, evPrep, 0);

    k_gather1<<<(NNODES * 32 + T - 1) / T, T>>>();

    {   // GEMM1: 128x128 tiles (full grid)
        dim3 grid(HID / 128, (NNODES + 127) / 128);
        k_mma<INDIM, HID, 128, true><<<grid, 256, SMEM1>>>(
            d_axh, d_axl, d_w1h, d_w1l, b1, a1, d_h1h, d_h1l, nullptr, NNODES);
    }
    {   // GEMM2: 128x64 tiles (full grid, 3 CTAs/SM)
        dim3 grid(OUTD / 64, (NNODES + 127) / 128);
        k_mma<HID, OUTD, 64, false><<<grid, 256, SMEM2>>>(
            d_h1h, d_h1l, d_w2h, d_w2l, nullptr, nullptr, nullptr, nullptr,
            d_h2, NNODES);
    }
    k_gather2<<<(NNODES * 32 + T - 1) / T, T>>>(b2, a2, out);
}

// round 14
// speedup vs baseline: 1.0525x; 1.0056x over previous
#include <cuda_runtime.h>
#include <cuda_bf16.h>
#include <cuda_fp16.h>
#include <cstdint>

// ---------------------------------------------------------------------------
// 2-layer GCN. R14 = R10 serial unfragmented pipeline + one fork placed per
// R12's measurement: prepd overlaps ONLY csr (scan runs uncontended).
//   s0: init -> deg -> scan -> csr ------------\
//   s1:                  \-> prepd ------------ join -> gather1 -> GEMM1 -> GEMM2 -> gather2
// ---------------------------------------------------------------------------

static constexpr int NNODES = 50000;
static constexpr int NEDGES = 800000;
static constexpr int INDIM  = 128;
static constexpr int ADDDIM = 8;
static constexpr int HID    = 256;
static constexpr int OUTD   = 128;

// -------------------- device scratch ----------------------------------------
__device__ __align__(16) __half g_xh[(size_t)NNODES * INDIM];
__device__ __align__(16) __nv_bfloat16 g_aggx_hi[(size_t)NNODES * INDIM];
__device__ __align__(16) __nv_bfloat16 g_aggx_lo[(size_t)NNODES * INDIM];
__device__ __align__(16) __nv_bfloat16 g_h1_hi[(size_t)NNODES * HID];
__device__ __align__(16) __nv_bfloat16 g_h1_lo[(size_t)NNODES * HID];
__device__ __align__(16) __half g_h2[(size_t)NNODES * OUTD];
__device__ float g_q[NNODES];
__device__ float g_dinv[NNODES];
__device__ int   g_deg[NNODES];
__device__ int   g_off[NNODES + 1];
__device__ int   g_cur[NNODES];
__device__ int   g_src[NEDGES];
__device__ float g_c1[HID];
__device__ __align__(16) __nv_bfloat16 g_wt1_hi[HID * INDIM], g_wt1_lo[HID * INDIM];
__device__ __align__(16) __nv_bfloat16 g_wt2_hi[OUTD * HID],  g_wt2_lo[OUTD * HID];
__device__ int g_is64;

// -------------------- asm helpers -------------------------------------------
__device__ __forceinline__ uint32_t smem_u32(const void* p) {
    return (uint32_t)__cvta_generic_to_shared(p);
}
__device__ __forceinline__ void ldsm_x4(uint32_t r[4], uint32_t addr) {
    asm volatile("ldmatrix.sync.aligned.m8n8.x4.shared.b16 {%0,%1,%2,%3}, [%4];"
                 : "=r"(r[0]), "=r"(r[1]), "=r"(r[2]), "=r"(r[3]) : "r"(addr));
}
__device__ __forceinline__ void mma_bf16(float* c, const uint32_t* a,
                                         uint32_t b0, uint32_t b1) {
    asm volatile(
        "mma.sync.aligned.m16n8k16.row.col.f32.bf16.bf16.f32 "
        "{%0,%1,%2,%3}, {%4,%5,%6,%7}, {%8,%9}, {%0,%1,%2,%3};"
        : "+f"(c[0]), "+f"(c[1]), "+f"(c[2]), "+f"(c[3])
        : "r"(a[0]), "r"(a[1]), "r"(a[2]), "r"(a[3]), "r"(b0), "r"(b1));
}
__device__ __forceinline__ void cp16(uint32_t dst, const void* src, uint32_t sz) {
    asm volatile("cp.async.cg.shared.global [%0], [%1], 16, %2;"
                 :: "r"(dst), "l"(src), "r"(sz) : "memory");
}
__device__ __forceinline__ void cp_commit() {
    asm volatile("cp.async.commit_group;" ::: "memory");
}
template <int N>
__device__ __forceinline__ void cp_wait() {
    asm volatile("cp.async.wait_group %0;" :: "n"(N) : "memory");
}

// -------------------- prep kernels ------------------------------------------
__global__ void k_init(const long long* __restrict__ ei) {
    int i = blockIdx.x * blockDim.x + threadIdx.x;
    if (i < NNODES) g_deg[i] = 0;
    if (blockIdx.x == 0 && threadIdx.x < 32) {
        bool bad = false;
        for (int j = threadIdx.x; j < 512; j += 32) {
            long long v = ei[j];
            if (v < 0 || v >= NNODES) bad = true;
        }
        unsigned m = __ballot_sync(0xFFFFFFFFu, bad);
        if (threadIdx.x == 0) g_is64 = (m == 0u) ? 1 : 0;
    }
}
// dense prep: x->fp16, weight split+transpose, c1 (depends only on inputs)
__global__ void k_prepd(const float* __restrict__ x,
                        const float* __restrict__ W1, const float* __restrict__ W2,
                        const float* __restrict__ idv) {
    constexpr int XT = NNODES * INDIM / 4;
    constexpr int N1 = HID * INDIM;
    constexpr int N2 = OUTD * HID;
    int idx = blockIdx.x * blockDim.x + threadIdx.x;
    if (idx < XT) {
        float4 v = __ldg((const float4*)x + idx);
        __half2 p0 = __floats2half2_rn(v.x, v.y);
        __half2 p1 = __floats2half2_rn(v.z, v.w);
        uint2 o;
        o.x = *(uint32_t*)&p0;
        o.y = *(uint32_t*)&p1;
        *((uint2*)g_xh + idx) = o;
    } else if (idx < XT + N1) {
        int j = idx - XT;
        int o = j / INDIM, i = j % INDIM;
        float v = W1[(size_t)i * HID + o];
        __nv_bfloat16 h = __float2bfloat16_rn(v);
        g_wt1_hi[j] = h;
        g_wt1_lo[j] = __float2bfloat16_rn(v - __bfloat162float(h));
    } else if (idx < XT + N1 + N2) {
        int j = idx - XT - N1;
        int o = j / HID, i = j % HID;
        float v = W2[(size_t)i * OUTD + o];
        __nv_bfloat16 h = __float2bfloat16_rn(v);
        g_wt2_hi[j] = h;
        g_wt2_lo[j] = __float2bfloat16_rn(v - __bfloat162float(h));
    } else if (idx < XT + N1 + N2 + HID) {
        int j = idx - XT - N1 - N2;
        float s = 0.f;
#pragma unroll
        for (int t = 0; t < ADDDIM; t++) s += idv[t] * W1[(size_t)(INDIM + t) * HID + j];
        g_c1[j] = s;
    }
}

__global__ void k_deg(const void* __restrict__ ei) {
    int i = blockIdx.x * blockDim.x + threadIdx.x;
    if (i >= NEDGES / 2) return;
    int d0, d1;
    if (g_is64) {
        longlong2 v = __ldg((const longlong2*)ei + NEDGES / 2 + i);
        d0 = (int)v.x; d1 = (int)v.y;
    } else {
        int2 v = __ldg((const int2*)ei + NEDGES / 2 + i);
        d0 = v.x; d1 = v.y;
    }
    atomicAdd(&g_deg[d0], 1);
    atomicAdd(&g_deg[d1], 1);
}
__global__ void k_scan() {
    __shared__ int warpsum[32];
    __shared__ int chunk_total;
    const int t = threadIdx.x;               // 1024
    const int lane = t & 31, wid = t >> 5;
    int run = 0;
    for (int base = 0; base < NNODES; base += 2048) {
        int i0 = base + t * 2, i1 = i0 + 1;
        int v0 = (i0 < NNODES) ? g_deg[i0] : 0;
        int v1 = (i1 < NNODES) ? g_deg[i1] : 0;
        if (i0 < NNODES) g_dinv[i0] = rsqrtf((float)(v0 + 1));
        if (i1 < NNODES) g_dinv[i1] = rsqrtf((float)(v1 + 1));
        int v = v0 + v1;
        int x = v;
#pragma unroll
        for (int o = 1; o < 32; o <<= 1) {
            int y = __shfl_up_sync(0xFFFFFFFFu, x, o);
            if (lane >= o) x += y;
        }
        if (lane == 31) warpsum[wid] = x;
        __syncthreads();
        if (wid == 0) {
            int w = warpsum[lane];
#pragma unroll
            for (int o = 1; o < 32; o <<= 1) {
                int y = __shfl_up_sync(0xFFFFFFFFu, w, o);
                if (lane >= o) w += y;
            }
            warpsum[lane] = w;
            if (lane == 31) chunk_total = w;
        }
        __syncthreads();
        int excl = run + (wid ? warpsum[wid - 1] : 0) + x - v;
        if (i0 < NNODES) { g_off[i0] = excl; g_cur[i0] = excl; }
        if (i1 < NNODES) { g_off[i1] = excl + v0; g_cur[i1] = excl + v0; }
        run += chunk_total;
        __syncthreads();
    }
    if (t == 0) g_off[NNODES] = run;
}
__global__ void k_csr(const void* __restrict__ ei) {
    int i = blockIdx.x * blockDim.x + threadIdx.x;
    if (i >= NEDGES / 2) return;
    int s0, s1, d0, d1;
    if (g_is64) {
        longlong2 sv = __ldg((const longlong2*)ei + i);
        longlong2 dv = __ldg((const longlong2*)ei + NEDGES / 2 + i);
        s0 = (int)sv.x; s1 = (int)sv.y; d0 = (int)dv.x; d1 = (int)dv.y;
    } else {
        int2 sv = __ldg((const int2*)ei + i);
        int2 dv = __ldg((const int2*)ei + NEDGES / 2 + i);
        s0 = sv.x; s1 = sv.y; d0 = dv.x; d1 = dv.y;
    }
    int p0 = atomicAdd(&g_cur[d0], 1);
    g_src[p0] = s0;
    int p1 = atomicAdd(&g_cur[d1], 1);
    g_src[p1] = s1;
}

// -------------------- gather1: agg(x fp16) -> bf16 hi/lo + q ----------------
__global__ __launch_bounds__(256) void k_gather1() {
    const int lane = threadIdx.x & 31;
    const int node = (blockIdx.x * blockDim.x + threadIdx.x) >> 5;
    if (node >= NNODES) return;
    const float dv = g_dinv[node];
    const int e0 = g_off[node], e1 = g_off[node + 1];
    float4 acc = make_float4(0.f, 0.f, 0.f, 0.f);
    float q = 0.f;

    auto rowfma = [&](int s, float w) {
        uint2 hv = __ldg((const uint2*)(g_xh + (size_t)s * INDIM) + lane);
        __half2 p0 = *(__half2*)&hv.x;
        __half2 p1 = *(__half2*)&hv.y;
        float2 f0 = __half22float2(p0);
        float2 f1 = __half22float2(p1);
        acc.x += f0.x * w; acc.y += f0.y * w;
        acc.z += f1.x * w; acc.w += f1.y * w;
    };

    int e = e0;
    for (; e + 4 <= e1; e += 4) {
        int s0 = __ldg(&g_src[e]),     s1 = __ldg(&g_src[e + 1]);
        int s2 = __ldg(&g_src[e + 2]), s3 = __ldg(&g_src[e + 3]);
        float w0 = __ldg(&g_dinv[s0]) * dv, w1 = __ldg(&g_dinv[s1]) * dv;
        float w2 = __ldg(&g_dinv[s2]) * dv, w3 = __ldg(&g_dinv[s3]) * dv;
        q += (w0 + w1) + (w2 + w3);
        rowfma(s0, w0); rowfma(s1, w1); rowfma(s2, w2); rowfma(s3, w3);
    }
    for (; e < e1; e++) {
        int s0 = __ldg(&g_src[e]);
        float w0 = __ldg(&g_dinv[s0]) * dv;
        q += w0;
        rowfma(s0, w0);
    }
    {
        float w = dv * dv;
        q += w;
        rowfma(node, w);
    }
    float vals[4] = {acc.x, acc.y, acc.z, acc.w};
    uint32_t hp[2], lp[2];
#pragma unroll
    for (int p = 0; p < 2; p++) {
        __nv_bfloat16 h0 = __float2bfloat16_rn(vals[p * 2]);
        __nv_bfloat16 h1 = __float2bfloat16_rn(vals[p * 2 + 1]);
        __nv_bfloat16 l0 = __float2bfloat16_rn(vals[p * 2] - __bfloat162float(h0));
        __nv_bfloat16 l1 = __float2bfloat16_rn(vals[p * 2 + 1] - __bfloat162float(h1));
        hp[p] = (uint32_t)__bfloat16_as_ushort(h0) | ((uint32_t)__bfloat16_as_ushort(h1) << 16);
        lp[p] = (uint32_t)__bfloat16_as_ushort(l0) | ((uint32_t)__bfloat16_as_ushort(l1) << 16);
    }
    size_t base = (size_t)node * INDIM + lane * 4;
    *(uint2*)&g_aggx_hi[base] = make_uint2(hp[0], hp[1]);
    *(uint2*)&g_aggx_lo[base] = make_uint2(lp[0], lp[1]);
    if (lane == 0) g_q[node] = q;
}

// -------------------- double-buffered split-bf16 GEMM -----------------------
template <int K, int NTOT, int BN, bool L1>
__global__ __launch_bounds__(256) void k_mma(
    const __nv_bfloat16* __restrict__ Ahi, const __nv_bfloat16* __restrict__ Alo,
    const __nv_bfloat16* __restrict__ Bhi, const __nv_bfloat16* __restrict__ Blo,
    const float* __restrict__ bias, const float* __restrict__ slope,
    __nv_bfloat16* __restrict__ OutHi, __nv_bfloat16* __restrict__ OutLo,
    __half* __restrict__ OutH, int M) {
    constexpr int BK = 32, SA = 40;
    constexpr int NSEG = K / BK;
    constexpr int TA = 128 * SA * 2;
    constexpr int TB = BN * SA * 2;
    constexpr int BUF = 2 * TA + 2 * TB;
    constexpr int NQ = BN / 32;

    extern __shared__ __align__(16) __nv_bfloat16 smem[];

    const int t = threadIdx.x;
    const int lane = t & 31, warp = t >> 5;
    const int wm0 = (warp >> 1) * 32;
    const int wn0 = (warp & 1) * (BN / 2);
    const int row0 = blockIdx.y * 128;
    const int n0 = blockIdx.x * BN;

    auto load_seg = [&](int seg, int b) {
        const int k0 = seg * BK;
        const uint32_t sbase = smem_u32(smem) + (uint32_t)b * BUF;
#pragma unroll
        for (int tl = 0; tl < 2; tl++) {
            const __nv_bfloat16* G = tl ? Alo : Ahi;
            uint32_t tbase = sbase + tl * TA;
#pragma unroll
            for (int c = t; c < 512; c += 256) {
                int r = c >> 2, ch = c & 3;
                int gr = row0 + r;
                uint32_t ok = (gr < M) ? 16u : 0u;
                cp16(tbase + r * (SA * 2) + ch * 16,
                     G + (size_t)gr * K + k0 + ch * 8, ok);
            }
        }
#pragma unroll
        for (int tl = 0; tl < 2; tl++) {
            const __nv_bfloat16* G = tl ? Blo : Bhi;
            uint32_t tbase = sbase + 2 * TA + tl * TB;
#pragma unroll
            for (int c = t; c < BN * 4; c += 256) {
                int r = c >> 2, ch = c & 3;
                cp16(tbase + r * (SA * 2) + ch * 16,
                     G + (size_t)(n0 + r) * K + k0 + ch * 8, 16u);
            }
        }
        cp_commit();
    };

    float acc[2][2 * NQ][4] = {};

    load_seg(0, 0);
    for (int s = 0; s < NSEG; s++) {
        const int b = s & 1;
        if (s + 1 < NSEG) load_seg(s + 1, b ^ 1);
        if (s + 1 < NSEG) cp_wait<1>(); else cp_wait<0>();
        __syncthreads();

        const uint32_t sb = smem_u32(smem) + (uint32_t)b * BUF;
        const uint32_t aHi = sb, aLo = sb + TA;
        const uint32_t bHi = sb + 2 * TA, bLo = sb + 2 * TA + TB;

#pragma unroll
        for (int ph = 0; ph < 3; ph++) {
            const uint32_t at = (ph == 1) ? aLo : aHi;
            const uint32_t bt = (ph == 2) ? bLo : bHi;
#pragma unroll
            for (int kh = 0; kh < 2; kh++) {
                uint32_t af[2][4], bf[NQ][4];
#pragma unroll
                for (int mi = 0; mi < 2; mi++) {
                    uint32_t addr = at +
                        ((wm0 + mi * 16 + (lane & 15)) * SA + kh * 16 + (lane >> 4) * 8) * 2;
                    ldsm_x4(af[mi], addr);
                }
#pragma unroll
                for (int nq = 0; nq < NQ; nq++) {
                    uint32_t addr = bt +
                        ((wn0 + nq * 16 + (lane & 7) + ((lane >> 4) & 1) * 8) * SA +
                         kh * 16 + ((lane >> 3) & 1) * 8) * 2;
                    ldsm_x4(bf[nq], addr);
                }
#pragma unroll
                for (int mi = 0; mi < 2; mi++)
#pragma unroll
                    for (int nq = 0; nq < NQ; nq++) {
                        mma_bf16(acc[mi][nq * 2],     af[mi], bf[nq][0], bf[nq][1]);
                        mma_bf16(acc[mi][nq * 2 + 1], af[mi], bf[nq][2], bf[nq][3]);
                    }
            }
        }
        __syncthreads();
    }

    float qv[2][2];
    if (L1) {
#pragma unroll
        for (int mi = 0; mi < 2; mi++) {
            int r0 = row0 + wm0 + mi * 16 + (lane >> 2);
            qv[mi][0] = (r0 < M) ? __ldg(&g_q[r0]) : 0.f;
            qv[mi][1] = (r0 + 8 < M) ? __ldg(&g_q[r0 + 8]) : 0.f;
        }
    }
#pragma unroll
    for (int mi = 0; mi < 2; mi++) {
        int r0 = row0 + wm0 + mi * 16 + (lane >> 2);
#pragma unroll
        for (int nt = 0; nt < 2 * NQ; nt++) {
            int c0 = n0 + wn0 + nt * 8 + (lane & 3) * 2;
            if (L1) {
                float cc0 = __ldg(&g_c1[c0]),   cc1 = __ldg(&g_c1[c0 + 1]);
                float bb0 = __ldg(&bias[c0]),   bb1 = __ldg(&bias[c0 + 1]);
                float ss0 = __ldg(&slope[c0]),  ss1 = __ldg(&slope[c0 + 1]);
#pragma unroll
                for (int h = 0; h < 2; h++) {
                    int r = r0 + h * 8;
                    if (r >= M) continue;
                    float v0 = acc[mi][nt][h * 2]     + qv[mi][h] * cc0 + bb0;
                    float v1 = acc[mi][nt][h * 2 + 1] + qv[mi][h] * cc1 + bb1;
                    v0 = v0 >= 0.f ? v0 : ss0 * v0;
                    v1 = v1 >= 0.f ? v1 : ss1 * v1;
                    __nv_bfloat16 h0 = __float2bfloat16_rn(v0);
                    __nv_bfloat16 h1 = __float2bfloat16_rn(v1);
                    __nv_bfloat16 l0 = __float2bfloat16_rn(v0 - __bfloat162float(h0));
                    __nv_bfloat16 l1 = __float2bfloat16_rn(v1 - __bfloat162float(h1));
                    size_t o = (size_t)r * NTOT + c0;
                    *(uint32_t*)(OutHi + o) = (uint32_t)__bfloat16_as_ushort(h0) |
                                              ((uint32_t)__bfloat16_as_ushort(h1) << 16);
                    *(uint32_t*)(OutLo + o) = (uint32_t)__bfloat16_as_ushort(l0) |
                                              ((uint32_t)__bfloat16_as_ushort(l1) << 16);
                }
            } else {
#pragma unroll
                for (int h = 0; h < 2; h++) {
                    int r = r0 + h * 8;
                    if (r >= M) continue;
                    __half2 hh = __floats2half2_rn(acc[mi][nt][h * 2],
                                                   acc[mi][nt][h * 2 + 1]);
                    *(uint32_t*)(OutH + (size_t)r * NTOT + c0) = *(uint32_t*)&hh;
                }
            }
        }
    }
}

// -------------------- gather2: fp16 h2 rows, fused bias+prelu ---------------
__global__ __launch_bounds__(256) void k_gather2(const float* __restrict__ bias,
                                                 const float* __restrict__ slope,
                                                 float* __restrict__ out) {
    const int lane = threadIdx.x & 31;
    const int node = (blockIdx.x * blockDim.x + threadIdx.x) >> 5;
    if (node >= NNODES) return;
    const float dv = g_dinv[node];
    const int e0 = g_off[node], e1 = g_off[node + 1];
    float4 acc = make_float4(0.f, 0.f, 0.f, 0.f);

    auto rowfma = [&](int s, float w) {
        uint2 hv = __ldg((const uint2*)(g_h2 + (size_t)s * OUTD) + lane);
        __half2 p0 = *(__half2*)&hv.x;
        __half2 p1 = *(__half2*)&hv.y;
        float2 f0 = __half22float2(p0);
        float2 f1 = __half22float2(p1);
        acc.x += f0.x * w; acc.y += f0.y * w;
        acc.z += f1.x * w; acc.w += f1.y * w;
    };

    int e = e0;
    for (; e + 4 <= e1; e += 4) {
        int s0 = __ldg(&g_src[e]),     s1 = __ldg(&g_src[e + 1]);
        int s2 = __ldg(&g_src[e + 2]), s3 = __ldg(&g_src[e + 3]);
        float w0 = __ldg(&g_dinv[s0]) * dv, w1 = __ldg(&g_dinv[s1]) * dv;
        float w2 = __ldg(&g_dinv[s2]) * dv, w3 = __ldg(&g_dinv[s3]) * dv;
        rowfma(s0, w0); rowfma(s1, w1); rowfma(s2, w2); rowfma(s3, w3);
    }
    for (; e < e1; e++) {
        int s0 = __ldg(&g_src[e]);
        float w0 = __ldg(&g_dinv[s0]) * dv;
        rowfma(s0, w0);
    }
    rowfma(node, dv * dv);

    float4 B = *(const float4*)&bias[lane * 4];
    float4 S = *(const float4*)&slope[lane * 4];
    float r0 = acc.x + B.x, r1 = acc.y + B.y, r2 = acc.z + B.z, r3 = acc.w + B.w;
    float4 o;
    o.x = r0 >= 0.f ? r0 : S.x * r0;
    o.y = r1 >= 0.f ? r1 : S.y * r1;
    o.z = r2 >= 0.f ? r2 : S.z * r2;
    o.w = r3 >= 0.f ? r3 : S.w * r3;
    *(float4*)&out[(size_t)node * OUTD + lane * 4] = o;
}

// -------------------- launch ------------------------------------------------
extern "C" void kernel_launch(void* const* d_in, const int* in_sizes, int n_in,
                              void* d_out, int out_size) {
    const float* x  = (const float*)d_in[0];
    const void*  ei = d_in[1];
    const float* idv = (const float*)d_in[2];
    const float* W1 = (const float*)d_in[3];
    const float* b1 = (const float*)d_in[4];
    const float* a1 = (const float*)d_in[5];
    const float* W2 = (const float*)d_in[6];
    const float* b2 = (const float*)d_in[7];
    const float* a2 = (const float*)d_in[8];
    float* out = (float*)d_out;

    __nv_bfloat16 *d_axh, *d_axl, *d_h1h, *d_h1l, *d_w1h, *d_w1l, *d_w2h, *d_w2l;
    __half *d_h2;
    cudaGetSymbolAddress((void**)&d_axh, g_aggx_hi);
    cudaGetSymbolAddress((void**)&d_axl, g_aggx_lo);
    cudaGetSymbolAddress((void**)&d_h1h, g_h1_hi);
    cudaGetSymbolAddress((void**)&d_h1l, g_h1_lo);
    cudaGetSymbolAddress((void**)&d_w1h, g_wt1_hi);
    cudaGetSymbolAddress((void**)&d_w1l, g_wt1_lo);
    cudaGetSymbolAddress((void**)&d_w2h, g_wt2_hi);
    cudaGetSymbolAddress((void**)&d_w2l, g_wt2_lo);
    cudaGetSymbolAddress((void**)&d_h2, g_h2);

    const int T = 256;
    constexpr int SMEM1 = 2 * (2 * 128 + 2 * 128) * 40 * 2;   // 81920 B
    constexpr int SMEM2 = 2 * (2 * 128 + 2 * 64) * 40 * 2;    // 61440 B

    static cudaStream_t s1 = nullptr;
    static cudaEvent_t evScan, evPrep;
    if (!s1) {
        cudaStreamCreate(&s1);
        cudaEventCreateWithFlags(&evScan, cudaEventDisableTiming);
        cudaEventCreateWithFlags(&evPrep, cudaEventDisableTiming);
        cudaFuncSetAttribute(k_mma<INDIM, HID, 128, true>,
                             cudaFuncAttributeMaxDynamicSharedMemorySize, SMEM1);
        cudaFuncSetAttribute(k_mma<HID, OUTD, 64, false>,
                             cudaFuncAttributeMaxDynamicSharedMemorySize, SMEM2);
    }

    // serial edge-chain prefix: scan runs with the chip otherwise idle
    k_init<<<(NNODES + T - 1) / T, T>>>((const long long*)ei);
    k_deg<<<(NEDGES / 2 + T - 1) / T, T>>>(ei);
    k_scan<<<1, 1024>>>();
    cudaEventRecord(evScan, 0);

    // fork: dense prep overlaps ONLY csr
    cudaStreamWaitEvent(s1, evScan, 0);
    {
        constexpr int TOT = NNODES * INDIM / 4 + HID * INDIM + OUTD * HID + HID;
        k_prepd<<<(TOT + T - 1) / T, T, 0, s1>>>(x, W1, W2, idv);
    }
    k_csr<<<(NEDGES / 2 + T - 1) / T, T>>>(ei);

    // join before gather1 (needs g_xh)
    cudaEventRecord(evPrep, s1);
    cudaStreamWaitEvent(0, evPrep, 0);

    // unfragmented compute chain (R10-proven)
    k_gather1<<<(NNODES * 32 + T - 1) / T, T>>>();

    {   // GEMM1: 128x128 tiles (full grid)
        dim3 grid(HID / 128, (NNODES + 127) / 128);
        k_mma<INDIM, HID, 128, true><<<grid, 256, SMEM1>>>(
            d_axh, d_axl, d_w1h, d_w1l, b1, a1, d_h1h, d_h1l, nullptr, NNODES);
    }
    {   // GEMM2: 128x64 tiles (full grid, 3 CTAs/SM)
        dim3 grid(OUTD / 64, (NNODES + 127) / 128);
        k_mma<HID, OUTD, 64, false><<<grid, 256, SMEM2>>>(
            d_h1h, d_h1l, d_w2h, d_w2l, nullptr, nullptr, nullptr, nullptr,
            d_h2, NNODES);
    }
    k_gather2<<<(NNODES * 32 + T - 1) / T, T>>>(b2, a2, out);
}

// round 16
// speedup vs baseline: 1.3868x; 1.3177x over previous
#include <cuda_runtime.h>
#include <cuda_fp16.h>
#include <cstdint>

// ---------------------------------------------------------------------------
// 2-layer GCN. R15 = R10 serial pipeline, GEMMs switched to single fp16 MMA
// (no compensated split): h1/h2/weights/activations all fp16, fp32 accum.
//   prep0 -> deg -> scan -> csr -> gather1 -> GEMM1 -> GEMM2 -> gather2
// ---------------------------------------------------------------------------

static constexpr int NNODES = 50000;
static constexpr int NEDGES = 800000;
static constexpr int INDIM  = 128;
static constexpr int ADDDIM = 8;
static constexpr int HID    = 256;
static constexpr int OUTD   = 128;

// -------------------- device scratch ----------------------------------------
__device__ __align__(16) __half g_xh[(size_t)NNODES * INDIM];   // fp16 x
__device__ __align__(16) __half g_ax[(size_t)NNODES * INDIM];   // aggregated x (GEMM1 A)
__device__ __align__(16) __half g_h1[(size_t)NNODES * HID];     // layer-1 act (GEMM2 A)
__device__ __align__(16) __half g_h2[(size_t)NNODES * OUTD];    // GEMM2 out
__device__ float g_q[NNODES];
__device__ float g_dinv[NNODES];
__device__ int   g_deg[NNODES];
__device__ int   g_off[NNODES + 1];
__device__ int   g_cur[NNODES];
__device__ int   g_src[NEDGES];
__device__ float g_c1[HID];
__device__ __align__(16) __half g_wt1[HID * INDIM];             // W1^T fp16 [256][128]
__device__ __align__(16) __half g_wt2[OUTD * HID];              // W2^T fp16 [128][256]
__device__ int g_is64;

// -------------------- asm helpers -------------------------------------------
__device__ __forceinline__ uint32_t smem_u32(const void* p) {
    return (uint32_t)__cvta_generic_to_shared(p);
}
__device__ __forceinline__ void ldsm_x4(uint32_t r[4], uint32_t addr) {
    asm volatile("ldmatrix.sync.aligned.m8n8.x4.shared.b16 {%0,%1,%2,%3}, [%4];"
                 : "=r"(r[0]), "=r"(r[1]), "=r"(r[2]), "=r"(r[3]) : "r"(addr));
}
__device__ __forceinline__ void mma_f16(float* c, const uint32_t* a,
                                        uint32_t b0, uint32_t b1) {
    asm volatile(
        "mma.sync.aligned.m16n8k16.row.col.f32.f16.f16.f32 "
        "{%0,%1,%2,%3}, {%4,%5,%6,%7}, {%8,%9}, {%0,%1,%2,%3};"
        : "+f"(c[0]), "+f"(c[1]), "+f"(c[2]), "+f"(c[3])
        : "r"(a[0]), "r"(a[1]), "r"(a[2]), "r"(a[3]), "r"(b0), "r"(b1));
}
__device__ __forceinline__ void cp16(uint32_t dst, const void* src, uint32_t sz) {
    asm volatile("cp.async.cg.shared.global [%0], [%1], 16, %2;"
                 :: "r"(dst), "l"(src), "r"(sz) : "memory");
}
__device__ __forceinline__ void cp_commit() {
    asm volatile("cp.async.commit_group;" ::: "memory");
}
template <int N>
__device__ __forceinline__ void cp_wait() {
    asm volatile("cp.async.wait_group %0;" :: "n"(N) : "memory");
}

// -------------------- merged prep: detect + zero deg + x->fp16 + weights ----
__global__ void k_prep0(const float* __restrict__ x, const long long* __restrict__ ei,
                        const float* __restrict__ W1, const float* __restrict__ W2,
                        const float* __restrict__ idv) {
    constexpr int XT = NNODES * INDIM / 4;
    constexpr int N1 = HID * INDIM;
    constexpr int N2 = OUTD * HID;
    int idx = blockIdx.x * blockDim.x + threadIdx.x;

    if (blockIdx.x == 0 && threadIdx.x < 32) {
        bool bad = false;
        for (int j = threadIdx.x; j < 512; j += 32) {
            long long v = ei[j];
            if (v < 0 || v >= NNODES) bad = true;
        }
        unsigned m = __ballot_sync(0xFFFFFFFFu, bad);
        if (threadIdx.x == 0) g_is64 = (m == 0u) ? 1 : 0;
    }

    if (idx < XT) {
        float4 v = __ldg((const float4*)x + idx);
        __half2 p0 = __floats2half2_rn(v.x, v.y);
        __half2 p1 = __floats2half2_rn(v.z, v.w);
        uint2 o;
        o.x = *(uint32_t*)&p0;
        o.y = *(uint32_t*)&p1;
        *((uint2*)g_xh + idx) = o;
    } else if (idx < XT + NNODES) {
        g_deg[idx - XT] = 0;
    } else if (idx < XT + NNODES + N1) {
        int j = idx - XT - NNODES;
        int o = j / INDIM, i = j % INDIM;
        g_wt1[j] = __float2half_rn(W1[(size_t)i * HID + o]);
    } else if (idx < XT + NNODES + N1 + N2) {
        int j = idx - XT - NNODES - N1;
        int o = j / HID, i = j % HID;
        g_wt2[j] = __float2half_rn(W2[(size_t)i * OUTD + o]);
    } else if (idx < XT + NNODES + N1 + N2 + HID) {
        int j = idx - XT - NNODES - N1 - N2;
        float s = 0.f;
#pragma unroll
        for (int t = 0; t < ADDDIM; t++) s += idv[t] * W1[(size_t)(INDIM + t) * HID + j];
        g_c1[j] = s;
    }
}

__global__ void k_deg(const void* __restrict__ ei) {
    int i = blockIdx.x * blockDim.x + threadIdx.x;
    if (i >= NEDGES / 2) return;
    int d0, d1;
    if (g_is64) {
        longlong2 v = __ldg((const longlong2*)ei + NEDGES / 2 + i);
        d0 = (int)v.x; d1 = (int)v.y;
    } else {
        int2 v = __ldg((const int2*)ei + NEDGES / 2 + i);
        d0 = v.x; d1 = v.y;
    }
    atomicAdd(&g_deg[d0], 1);
    atomicAdd(&g_deg[d1], 1);
}
__global__ void k_scan() {
    __shared__ int warpsum[32];
    __shared__ int chunk_total;
    const int t = threadIdx.x;               // 1024
    const int lane = t & 31, wid = t >> 5;
    int run = 0;
    for (int base = 0; base < NNODES; base += 2048) {
        int i0 = base + t * 2, i1 = i0 + 1;
        int v0 = (i0 < NNODES) ? g_deg[i0] : 0;
        int v1 = (i1 < NNODES) ? g_deg[i1] : 0;
        if (i0 < NNODES) g_dinv[i0] = rsqrtf((float)(v0 + 1));
        if (i1 < NNODES) g_dinv[i1] = rsqrtf((float)(v1 + 1));
        int v = v0 + v1;
        int x = v;
#pragma unroll
        for (int o = 1; o < 32; o <<= 1) {
            int y = __shfl_up_sync(0xFFFFFFFFu, x, o);
            if (lane >= o) x += y;
        }
        if (lane == 31) warpsum[wid] = x;
        __syncthreads();
        if (wid == 0) {
            int w = warpsum[lane];
#pragma unroll
            for (int o = 1; o < 32; o <<= 1) {
                int y = __shfl_up_sync(0xFFFFFFFFu, w, o);
                if (lane >= o) w += y;
            }
            warpsum[lane] = w;
            if (lane == 31) chunk_total = w;
        }
        __syncthreads();
        int excl = run + (wid ? warpsum[wid - 1] : 0) + x - v;
        if (i0 < NNODES) { g_off[i0] = excl; g_cur[i0] = excl; }
        if (i1 < NNODES) { g_off[i1] = excl + v0; g_cur[i1] = excl + v0; }
        run += chunk_total;
        __syncthreads();
    }
    if (t == 0) g_off[NNODES] = run;
}
__global__ void k_csr(const void* __restrict__ ei) {
    int i = blockIdx.x * blockDim.x + threadIdx.x;
    if (i >= NEDGES / 2) return;
    int s0, s1, d0, d1;
    if (g_is64) {
        longlong2 sv = __ldg((const longlong2*)ei + i);
        longlong2 dv = __ldg((const longlong2*)ei + NEDGES / 2 + i);
        s0 = (int)sv.x; s1 = (int)sv.y; d0 = (int)dv.x; d1 = (int)dv.y;
    } else {
        int2 sv = __ldg((const int2*)ei + i);
        int2 dv = __ldg((const int2*)ei + NEDGES / 2 + i);
        s0 = sv.x; s1 = sv.y; d0 = dv.x; d1 = dv.y;
    }
    int p0 = atomicAdd(&g_cur[d0], 1);
    g_src[p0] = s0;
    int p1 = atomicAdd(&g_cur[d1], 1);
    g_src[p1] = s1;
}

// -------------------- gather1: agg(x fp16) -> fp16 + q ----------------------
__global__ __launch_bounds__(256) void k_gather1() {
    const int lane = threadIdx.x & 31;
    const int node = (blockIdx.x * blockDim.x + threadIdx.x) >> 5;
    if (node >= NNODES) return;
    const float dv = g_dinv[node];
    const int e0 = g_off[node], e1 = g_off[node + 1];
    float4 acc = make_float4(0.f, 0.f, 0.f, 0.f);
    float q = 0.f;

    auto rowfma = [&](int s, float w) {
        uint2 hv = __ldg((const uint2*)(g_xh + (size_t)s * INDIM) + lane);
        __half2 p0 = *(__half2*)&hv.x;
        __half2 p1 = *(__half2*)&hv.y;
        float2 f0 = __half22float2(p0);
        float2 f1 = __half22float2(p1);
        acc.x += f0.x * w; acc.y += f0.y * w;
        acc.z += f1.x * w; acc.w += f1.y * w;
    };

    int e = e0;
    for (; e + 4 <= e1; e += 4) {
        int s0 = __ldg(&g_src[e]),     s1 = __ldg(&g_src[e + 1]);
        int s2 = __ldg(&g_src[e + 2]), s3 = __ldg(&g_src[e + 3]);
        float w0 = __ldg(&g_dinv[s0]) * dv, w1 = __ldg(&g_dinv[s1]) * dv;
        float w2 = __ldg(&g_dinv[s2]) * dv, w3 = __ldg(&g_dinv[s3]) * dv;
        q += (w0 + w1) + (w2 + w3);
        rowfma(s0, w0); rowfma(s1, w1); rowfma(s2, w2); rowfma(s3, w3);
    }
    for (; e < e1; e++) {
        int s0 = __ldg(&g_src[e]);
        float w0 = __ldg(&g_dinv[s0]) * dv;
        q += w0;
        rowfma(s0, w0);
    }
    {
        float w = dv * dv;
        q += w;
        rowfma(node, w);
    }
    __half2 o0 = __floats2half2_rn(acc.x, acc.y);
    __half2 o1 = __floats2half2_rn(acc.z, acc.w);
    uint2 ov;
    ov.x = *(uint32_t*)&o0;
    ov.y = *(uint32_t*)&o1;
    *((uint2*)(g_ax + (size_t)node * INDIM) + lane) = ov;
    if (lane == 0) g_q[node] = q;
}

// -------------------- double-buffered fp16 GEMM -----------------------------
// C[M,NTOT] = A[M,K] @ B[NTOT,K]^T, fp16 operands, fp32 accum.
// CTA tile 128 x BN, 8 warps in 4x2, BK=32, SA=40 half stride.
// L1: out = prelu(D + q*c1 + bias) fp16. else: out = D fp16.
template <int K, int NTOT, int BN, bool L1>
__global__ __launch_bounds__(256) void k_mma(
    const __half* __restrict__ A, const __half* __restrict__ B,
    const float* __restrict__ bias, const float* __restrict__ slope,
    __half* __restrict__ Out, int M) {
    constexpr int BK = 32, SA = 40;
    constexpr int NSEG = K / BK;
    constexpr int TA = 128 * SA * 2;            // A tile bytes
    constexpr int TB = BN * SA * 2;             // B tile bytes
    constexpr int BUF = TA + TB;
    constexpr int NQ = BN / 32;

    extern __shared__ __align__(16) __half smem[];

    const int t = threadIdx.x;
    const int lane = t & 31, warp = t >> 5;
    const int wm0 = (warp >> 1) * 32;
    const int wn0 = (warp & 1) * (BN / 2);
    const int row0 = blockIdx.y * 128;
    const int n0 = blockIdx.x * BN;

    auto load_seg = [&](int seg, int b) {
        const int k0 = seg * BK;
        const uint32_t sbase = smem_u32(smem) + (uint32_t)b * BUF;
        // A tile: 128 rows x 4 chunks (16B)
#pragma unroll
        for (int c = t; c < 512; c += 256) {
            int r = c >> 2, ch = c & 3;
            int gr = row0 + r;
            uint32_t ok = (gr < M) ? 16u : 0u;
            cp16(sbase + r * (SA * 2) + ch * 16,
                 A + (size_t)gr * K + k0 + ch * 8, ok);
        }
        // B tile: BN rows x 4 chunks
#pragma unroll
        for (int c = t; c < BN * 4; c += 256) {
            int r = c >> 2, ch = c & 3;
            cp16(sbase + TA + r * (SA * 2) + ch * 16,
                 B + (size_t)(n0 + r) * K + k0 + ch * 8, 16u);
        }
        cp_commit();
    };

    float acc[2][2 * NQ][4] = {};

    load_seg(0, 0);
    for (int s = 0; s < NSEG; s++) {
        const int b = s & 1;
        if (s + 1 < NSEG) load_seg(s + 1, b ^ 1);
        if (s + 1 < NSEG) cp_wait<1>(); else cp_wait<0>();
        __syncthreads();

        const uint32_t sb = smem_u32(smem) + (uint32_t)b * BUF;
        const uint32_t at = sb, bt = sb + TA;

#pragma unroll
        for (int kh = 0; kh < 2; kh++) {
            uint32_t af[2][4], bf[NQ][4];
#pragma unroll
            for (int mi = 0; mi < 2; mi++) {
                uint32_t addr = at +
                    ((wm0 + mi * 16 + (lane & 15)) * SA + kh * 16 + (lane >> 4) * 8) * 2;
                ldsm_x4(af[mi], addr);
            }
#pragma unroll
            for (int nq = 0; nq < NQ; nq++) {
                uint32_t addr = bt +
                    ((wn0 + nq * 16 + (lane & 7) + ((lane >> 4) & 1) * 8) * SA +
                     kh * 16 + ((lane >> 3) & 1) * 8) * 2;
                ldsm_x4(bf[nq], addr);
            }
#pragma unroll
            for (int mi = 0; mi < 2; mi++)
#pragma unroll
                for (int nq = 0; nq < NQ; nq++) {
                    mma_f16(acc[mi][nq * 2],     af[mi], bf[nq][0], bf[nq][1]);
                    mma_f16(acc[mi][nq * 2 + 1], af[mi], bf[nq][2], bf[nq][3]);
                }
        }
        __syncthreads();
    }

    // epilogue
    float qv[2][2];
    if (L1) {
#pragma unroll
        for (int mi = 0; mi < 2; mi++) {
            int r0 = row0 + wm0 + mi * 16 + (lane >> 2);
            qv[mi][0] = (r0 < M) ? __ldg(&g_q[r0]) : 0.f;
            qv[mi][1] = (r0 + 8 < M) ? __ldg(&g_q[r0 + 8]) : 0.f;
        }
    }
#pragma unroll
    for (int mi = 0; mi < 2; mi++) {
        int r0 = row0 + wm0 + mi * 16 + (lane >> 2);
#pragma unroll
        for (int nt = 0; nt < 2 * NQ; nt++) {
            int c0 = n0 + wn0 + nt * 8 + (lane & 3) * 2;
            if (L1) {
                float cc0 = __ldg(&g_c1[c0]),   cc1 = __ldg(&g_c1[c0 + 1]);
                float bb0 = __ldg(&bias[c0]),   bb1 = __ldg(&bias[c0 + 1]);
                float ss0 = __ldg(&slope[c0]),  ss1 = __ldg(&slope[c0 + 1]);
#pragma unroll
                for (int h = 0; h < 2; h++) {
                    int r = r0 + h * 8;
                    if (r >= M) continue;
                    float v0 = acc[mi][nt][h * 2]     + qv[mi][h] * cc0 + bb0;
                    float v1 = acc[mi][nt][h * 2 + 1] + qv[mi][h] * cc1 + bb1;
                    v0 = v0 >= 0.f ? v0 : ss0 * v0;
                    v1 = v1 >= 0.f ? v1 : ss1 * v1;
                    __half2 hh = __floats2half2_rn(v0, v1);
                    *(uint32_t*)(Out + (size_t)r * NTOT + c0) = *(uint32_t*)&hh;
                }
            } else {
#pragma unroll
                for (int h = 0; h < 2; h++) {
                    int r = r0 + h * 8;
                    if (r >= M) continue;
                    __half2 hh = __floats2half2_rn(acc[mi][nt][h * 2],
                                                   acc[mi][nt][h * 2 + 1]);
                    *(uint32_t*)(Out + (size_t)r * NTOT + c0) = *(uint32_t*)&hh;
                }
            }
        }
    }
}

// -------------------- gather2: fp16 h2 rows, fused bias+prelu ---------------
__global__ __launch_bounds__(256) void k_gather2(const float* __restrict__ bias,
                                                 const float* __restrict__ slope,
                                                 float* __restrict__ out) {
    const int lane = threadIdx.x & 31;
    const int node = (blockIdx.x * blockDim.x + threadIdx.x) >> 5;
    if (node >= NNODES) return;
    const float dv = g_dinv[node];
    const int e0 = g_off[node], e1 = g_off[node + 1];
    float4 acc = make_float4(0.f, 0.f, 0.f, 0.f);

    auto rowfma = [&](int s, float w) {
        uint2 hv = __ldg((const uint2*)(g_h2 + (size_t)s * OUTD) + lane);
        __half2 p0 = *(__half2*)&hv.x;
        __half2 p1 = *(__half2*)&hv.y;
        float2 f0 = __half22float2(p0);
        float2 f1 = __half22float2(p1);
        acc.x += f0.x * w; acc.y += f0.y * w;
        acc.z += f1.x * w; acc.w += f1.y * w;
    };

    int e = e0;
    for (; e + 4 <= e1; e += 4) {
        int s0 = __ldg(&g_src[e]),     s1 = __ldg(&g_src[e + 1]);
        int s2 = __ldg(&g_src[e + 2]), s3 = __ldg(&g_src[e + 3]);
        float w0 = __ldg(&g_dinv[s0]) * dv, w1 = __ldg(&g_dinv[s1]) * dv;
        float w2 = __ldg(&g_dinv[s2]) * dv, w3 = __ldg(&g_dinv[s3]) * dv;
        rowfma(s0, w0); rowfma(s1, w1); rowfma(s2, w2); rowfma(s3, w3);
    }
    for (; e < e1; e++) {
        int s0 = __ldg(&g_src[e]);
        float w0 = __ldg(&g_dinv[s0]) * dv;
        rowfma(s0, w0);
    }
    rowfma(node, dv * dv);

    float4 B = *(const float4*)&bias[lane * 4];
    float4 S = *(const float4*)&slope[lane * 4];
    float r0 = acc.x + B.x, r1 = acc.y + B.y, r2 = acc.z + B.z, r3 = acc.w + B.w;
    float4 o;
    o.x = r0 >= 0.f ? r0 : S.x * r0;
    o.y = r1 >= 0.f ? r1 : S.y * r1;
    o.z = r2 >= 0.f ? r2 : S.z * r2;
    o.w = r3 >= 0.f ? r3 : S.w * r3;
    *(float4*)&out[(size_t)node * OUTD + lane * 4] = o;
}

// -------------------- launch ------------------------------------------------
extern "C" void kernel_launch(void* const* d_in, const int* in_sizes, int n_in,
                              void* d_out, int out_size) {
    const float* x  = (const float*)d_in[0];
    const void*  ei = d_in[1];
    const float* idv = (const float*)d_in[2];
    const float* W1 = (const float*)d_in[3];
    const float* b1 = (const float*)d_in[4];
    const float* a1 = (const float*)d_in[5];
    const float* W2 = (const float*)d_in[6];
    const float* b2 = (const float*)d_in[7];
    const float* a2 = (const float*)d_in[8];
    float* out = (float*)d_out;

    __half *d_ax, *d_h1, *d_h2, *d_w1, *d_w2;
    cudaGetSymbolAddress((void**)&d_ax, g_ax);
    cudaGetSymbolAddress((void**)&d_h1, g_h1);
    cudaGetSymbolAddress((void**)&d_h2, g_h2);
    cudaGetSymbolAddress((void**)&d_w1, g_wt1);
    cudaGetSymbolAddress((void**)&d_w2, g_wt2);

    const int T = 256;
    constexpr int SMEM1 = 2 * (128 + 128) * 40 * 2;   // 40960 B
    constexpr int SMEM2 = 2 * (128 + 64) * 40 * 2;    // 30720 B

    static bool attr_done = false;
    if (!attr_done) {
        cudaFuncSetAttribute(k_mma<INDIM, HID, 128, true>,
                             cudaFuncAttributeMaxDynamicSharedMemorySize, SMEM1);
        cudaFuncSetAttribute(k_mma<HID, OUTD, 64, false>,
                             cudaFuncAttributeMaxDynamicSharedMemorySize, SMEM2);
        attr_done = true;
    }

    {
        constexpr int TOT = NNODES * INDIM / 4 + NNODES +
                            HID * INDIM + OUTD * HID + HID;
        k_prep0<<<(TOT + T - 1) / T, T>>>(x, (const long long*)ei, W1, W2, idv);
    }
    k_deg<<<(NEDGES / 2 + T - 1) / T, T>>>(ei);
    k_scan<<<1, 1024>>>();
    k_csr<<<(NEDGES / 2 + T - 1) / T, T>>>(ei);

    k_gather1<<<(NNODES * 32 + T - 1) / T, T>>>();

    {   // GEMM1: [50000,128] @ [256,128]^T -> h1 fp16 (fused q*c1+b1+prelu)
        dim3 grid(HID / 128, (NNODES + 127) / 128);
        k_mma<INDIM, HID, 128, true><<<grid, 256, SMEM1>>>(
            d_ax, d_w1, b1, a1, d_h1, NNODES);
    }
    {   // GEMM2: [50000,256] @ [128,256]^T -> h2 fp16
        dim3 grid(OUTD / 64, (NNODES + 127) / 128);
        k_mma<HID, OUTD, 64, false><<<grid, 256, SMEM2>>>(
            d_h1, d_w2, nullptr, nullptr, d_h2, NNODES);
    }
    k_gather2<<<(NNODES * 32 + T - 1) / T, T>>>(b2, a2, out);
}

// round 17
// speedup vs baseline: 1.3950x; 1.0059x over previous
#include <cuda_runtime.h>
#include <cuda_fp16.h>
#include <cstdint>

// ---------------------------------------------------------------------------
// 2-layer GCN. R17 = R16 (fp16 MMA pipeline) + MLP boosts:
//   deg/csr 4 edges/thread, gathers unrolled x8.
//   prep0 -> deg -> scan -> csr -> gather1 -> GEMM1 -> GEMM2 -> gather2
// ---------------------------------------------------------------------------

static constexpr int NNODES = 50000;
static constexpr int NEDGES = 800000;
static constexpr int INDIM  = 128;
static constexpr int ADDDIM = 8;
static constexpr int HID    = 256;
static constexpr int OUTD   = 128;

// -------------------- device scratch ----------------------------------------
__device__ __align__(16) __half g_xh[(size_t)NNODES * INDIM];
__device__ __align__(16) __half g_ax[(size_t)NNODES * INDIM];
__device__ __align__(16) __half g_h1[(size_t)NNODES * HID];
__device__ __align__(16) __half g_h2[(size_t)NNODES * OUTD];
__device__ float g_q[NNODES];
__device__ float g_dinv[NNODES];
__device__ int   g_deg[NNODES];
__device__ int   g_off[NNODES + 1];
__device__ int   g_cur[NNODES];
__device__ int   g_src[NEDGES];
__device__ float g_c1[HID];
__device__ __align__(16) __half g_wt1[HID * INDIM];
__device__ __align__(16) __half g_wt2[OUTD * HID];
__device__ int g_is64;

// -------------------- asm helpers -------------------------------------------
__device__ __forceinline__ uint32_t smem_u32(const void* p) {
    return (uint32_t)__cvta_generic_to_shared(p);
}
__device__ __forceinline__ void ldsm_x4(uint32_t r[4], uint32_t addr) {
    asm volatile("ldmatrix.sync.aligned.m8n8.x4.shared.b16 {%0,%1,%2,%3}, [%4];"
                 : "=r"(r[0]), "=r"(r[1]), "=r"(r[2]), "=r"(r[3]) : "r"(addr));
}
__device__ __forceinline__ void mma_f16(float* c, const uint32_t* a,
                                        uint32_t b0, uint32_t b1) {
    asm volatile(
        "mma.sync.aligned.m16n8k16.row.col.f32.f16.f16.f32 "
        "{%0,%1,%2,%3}, {%4,%5,%6,%7}, {%8,%9}, {%0,%1,%2,%3};"
        : "+f"(c[0]), "+f"(c[1]), "+f"(c[2]), "+f"(c[3])
        : "r"(a[0]), "r"(a[1]), "r"(a[2]), "r"(a[3]), "r"(b0), "r"(b1));
}
__device__ __forceinline__ void cp16(uint32_t dst, const void* src, uint32_t sz) {
    asm volatile("cp.async.cg.shared.global [%0], [%1], 16, %2;"
                 :: "r"(dst), "l"(src), "r"(sz) : "memory");
}
__device__ __forceinline__ void cp_commit() {
    asm volatile("cp.async.commit_group;" ::: "memory");
}
template <int N>
__device__ __forceinline__ void cp_wait() {
    asm volatile("cp.async.wait_group %0;" :: "n"(N) : "memory");
}

// -------------------- merged prep: detect + zero deg + x->fp16 + weights ----
__global__ void k_prep0(const float* __restrict__ x, const long long* __restrict__ ei,
                        const float* __restrict__ W1, const float* __restrict__ W2,
                        const float* __restrict__ idv) {
    constexpr int XT = NNODES * INDIM / 4;
    constexpr int N1 = HID * INDIM;
    constexpr int N2 = OUTD * HID;
    int idx = blockIdx.x * blockDim.x + threadIdx.x;

    if (blockIdx.x == 0 && threadIdx.x < 32) {
        bool bad = false;
        for (int j = threadIdx.x; j < 512; j += 32) {
            long long v = ei[j];
            if (v < 0 || v >= NNODES) bad = true;
        }
        unsigned m = __ballot_sync(0xFFFFFFFFu, bad);
        if (threadIdx.x == 0) g_is64 = (m == 0u) ? 1 : 0;
    }

    if (idx < XT) {
        float4 v = __ldg((const float4*)x + idx);
        __half2 p0 = __floats2half2_rn(v.x, v.y);
        __half2 p1 = __floats2half2_rn(v.z, v.w);
        uint2 o;
        o.x = *(uint32_t*)&p0;
        o.y = *(uint32_t*)&p1;
        *((uint2*)g_xh + idx) = o;
    } else if (idx < XT + NNODES) {
        g_deg[idx - XT] = 0;
    } else if (idx < XT + NNODES + N1) {
        int j = idx - XT - NNODES;
        int o = j / INDIM, i = j % INDIM;
        g_wt1[j] = __float2half_rn(W1[(size_t)i * HID + o]);
    } else if (idx < XT + NNODES + N1 + N2) {
        int j = idx - XT - NNODES - N1;
        int o = j / HID, i = j % HID;
        g_wt2[j] = __float2half_rn(W2[(size_t)i * OUTD + o]);
    } else if (idx < XT + NNODES + N1 + N2 + HID) {
        int j = idx - XT - NNODES - N1 - N2;
        float s = 0.f;
#pragma unroll
        for (int t = 0; t < ADDDIM; t++) s += idv[t] * W1[(size_t)(INDIM + t) * HID + j];
        g_c1[j] = s;
    }
}

// 4 edges per thread
__global__ void k_deg(const void* __restrict__ ei) {
    int i = blockIdx.x * blockDim.x + threadIdx.x;       // quad index
    if (i >= NEDGES / 4) return;
    int d[4];
    if (g_is64) {
        longlong2 v0 = __ldg((const longlong2*)ei + NEDGES / 2 + i * 2);
        longlong2 v1 = __ldg((const longlong2*)ei + NEDGES / 2 + i * 2 + 1);
        d[0] = (int)v0.x; d[1] = (int)v0.y; d[2] = (int)v1.x; d[3] = (int)v1.y;
    } else {
        int4 v = __ldg((const int4*)ei + NEDGES / 4 + i);
        d[0] = v.x; d[1] = v.y; d[2] = v.z; d[3] = v.w;
    }
#pragma unroll
    for (int k = 0; k < 4; k++) atomicAdd(&g_deg[d[k]], 1);
}
__global__ void k_scan() {
    __shared__ int warpsum[32];
    __shared__ int chunk_total;
    const int t = threadIdx.x;               // 1024
    const int lane = t & 31, wid = t >> 5;
    int run = 0;
    for (int base = 0; base < NNODES; base += 2048) {
        int i0 = base + t * 2, i1 = i0 + 1;
        int v0 = (i0 < NNODES) ? g_deg[i0] : 0;
        int v1 = (i1 < NNODES) ? g_deg[i1] : 0;
        if (i0 < NNODES) g_dinv[i0] = rsqrtf((float)(v0 + 1));
        if (i1 < NNODES) g_dinv[i1] = rsqrtf((float)(v1 + 1));
        int v = v0 + v1;
        int x = v;
#pragma unroll
        for (int o = 1; o < 32; o <<= 1) {
            int y = __shfl_up_sync(0xFFFFFFFFu, x, o);
            if (lane >= o) x += y;
        }
        if (lane == 31) warpsum[wid] = x;
        __syncthreads();
        if (wid == 0) {
            int w = warpsum[lane];
#pragma unroll
            for (int o = 1; o < 32; o <<= 1) {
                int y = __shfl_up_sync(0xFFFFFFFFu, w, o);
                if (lane >= o) w += y;
            }
            warpsum[lane] = w;
            if (lane == 31) chunk_total = w;
        }
        __syncthreads();
        int excl = run + (wid ? warpsum[wid - 1] : 0) + x - v;
        if (i0 < NNODES) { g_off[i0] = excl; g_cur[i0] = excl; }
        if (i1 < NNODES) { g_off[i1] = excl + v0; g_cur[i1] = excl + v0; }
        run += chunk_total;
        __syncthreads();
    }
    if (t == 0) g_off[NNODES] = run;
}
// 4 edges per thread
__global__ void k_csr(const void* __restrict__ ei) {
    int i = blockIdx.x * blockDim.x + threadIdx.x;       // quad index
    if (i >= NEDGES / 4) return;
    int s[4], d[4];
    if (g_is64) {
        longlong2 s0 = __ldg((const longlong2*)ei + i * 2);
        longlong2 s1 = __ldg((const longlong2*)ei + i * 2 + 1);
        longlong2 d0 = __ldg((const longlong2*)ei + NEDGES / 2 + i * 2);
        longlong2 d1 = __ldg((const longlong2*)ei + NEDGES / 2 + i * 2 + 1);
        s[0] = (int)s0.x; s[1] = (int)s0.y; s[2] = (int)s1.x; s[3] = (int)s1.y;
        d[0] = (int)d0.x; d[1] = (int)d0.y; d[2] = (int)d1.x; d[3] = (int)d1.y;
    } else {
        int4 sv = __ldg((const int4*)ei + i);
        int4 dv = __ldg((const int4*)ei + NEDGES / 4 + i);
        s[0] = sv.x; s[1] = sv.y; s[2] = sv.z; s[3] = sv.w;
        d[0] = dv.x; d[1] = dv.y; d[2] = dv.z; d[3] = dv.w;
    }
    int p[4];
#pragma unroll
    for (int k = 0; k < 4; k++) p[k] = atomicAdd(&g_cur[d[k]], 1);
#pragma unroll
    for (int k = 0; k < 4; k++) g_src[p[k]] = s[k];
}

// -------------------- gather1: agg(x fp16) -> fp16 + q (x8 unroll) ----------
__global__ __launch_bounds__(256) void k_gather1() {
    const int lane = threadIdx.x & 31;
    const int node = (blockIdx.x * blockDim.x + threadIdx.x) >> 5;
    if (node >= NNODES) return;
    const float dv = g_dinv[node];
    const int e0 = g_off[node], e1 = g_off[node + 1];
    float4 acc = make_float4(0.f, 0.f, 0.f, 0.f);
    float q = 0.f;

    auto rowfma = [&](int s, float w) {
        uint2 hv = __ldg((const uint2*)(g_xh + (size_t)s * INDIM) + lane);
        __half2 p0 = *(__half2*)&hv.x;
        __half2 p1 = *(__half2*)&hv.y;
        float2 f0 = __half22float2(p0);
        float2 f1 = __half22float2(p1);
        acc.x += f0.x * w; acc.y += f0.y * w;
        acc.z += f1.x * w; acc.w += f1.y * w;
    };

    int e = e0;
    for (; e + 8 <= e1; e += 8) {
        int s[8];
        float w[8];
#pragma unroll
        for (int k = 0; k < 8; k++) s[k] = __ldg(&g_src[e + k]);
#pragma unroll
        for (int k = 0; k < 8; k++) w[k] = __ldg(&g_dinv[s[k]]) * dv;
#pragma unroll
        for (int k = 0; k < 8; k++) q += w[k];
#pragma unroll
        for (int k = 0; k < 8; k++) rowfma(s[k], w[k]);
    }
    for (; e < e1; e++) {
        int s0 = __ldg(&g_src[e]);
        float w0 = __ldg(&g_dinv[s0]) * dv;
        q += w0;
        rowfma(s0, w0);
    }
    {
        float w = dv * dv;
        q += w;
        rowfma(node, w);
    }
    __half2 o0 = __floats2half2_rn(acc.x, acc.y);
    __half2 o1 = __floats2half2_rn(acc.z, acc.w);
    uint2 ov;
    ov.x = *(uint32_t*)&o0;
    ov.y = *(uint32_t*)&o1;
    *((uint2*)(g_ax + (size_t)node * INDIM) + lane) = ov;
    if (lane == 0) g_q[node] = q;
}

// -------------------- double-buffered fp16 GEMM -----------------------------
template <int K, int NTOT, int BN, bool L1>
__global__ __launch_bounds__(256) void k_mma(
    const __half* __restrict__ A, const __half* __restrict__ B,
    const float* __restrict__ bias, const float* __restrict__ slope,
    __half* __restrict__ Out, int M) {
    constexpr int BK = 32, SA = 40;
    constexpr int NSEG = K / BK;
    constexpr int TA = 128 * SA * 2;
    constexpr int TB = BN * SA * 2;
    constexpr int BUF = TA + TB;
    constexpr int NQ = BN / 32;

    extern __shared__ __align__(16) __half smem[];

    const int t = threadIdx.x;
    const int lane = t & 31, warp = t >> 5;
    const int wm0 = (warp >> 1) * 32;
    const int wn0 = (warp & 1) * (BN / 2);
    const int row0 = blockIdx.y * 128;
    const int n0 = blockIdx.x * BN;

    auto load_seg = [&](int seg, int b) {
        const int k0 = seg * BK;
        const uint32_t sbase = smem_u32(smem) + (uint32_t)b * BUF;
#pragma unroll
        for (int c = t; c < 512; c += 256) {
            int r = c >> 2, ch = c & 3;
            int gr = row0 + r;
            uint32_t ok = (gr < M) ? 16u : 0u;
            cp16(sbase + r * (SA * 2) + ch * 16,
                 A + (size_t)gr * K + k0 + ch * 8, ok);
        }
#pragma unroll
        for (int c = t; c < BN * 4; c += 256) {
            int r = c >> 2, ch = c & 3;
            cp16(sbase + TA + r * (SA * 2) + ch * 16,
                 B + (size_t)(n0 + r) * K + k0 + ch * 8, 16u);
        }
        cp_commit();
    };

    float acc[2][2 * NQ][4] = {};

    load_seg(0, 0);
    for (int s = 0; s < NSEG; s++) {
        const int b = s & 1;
        if (s + 1 < NSEG) load_seg(s + 1, b ^ 1);
        if (s + 1 < NSEG) cp_wait<1>(); else cp_wait<0>();
        __syncthreads();

        const uint32_t sb = smem_u32(smem) + (uint32_t)b * BUF;
        const uint32_t at = sb, bt = sb + TA;

#pragma unroll
        for (int kh = 0; kh < 2; kh++) {
            uint32_t af[2][4], bf[NQ][4];
#pragma unroll
            for (int mi = 0; mi < 2; mi++) {
                uint32_t addr = at +
                    ((wm0 + mi * 16 + (lane & 15)) * SA + kh * 16 + (lane >> 4) * 8) * 2;
                ldsm_x4(af[mi], addr);
            }
#pragma unroll
            for (int nq = 0; nq < NQ; nq++) {
                uint32_t addr = bt +
                    ((wn0 + nq * 16 + (lane & 7) + ((lane >> 4) & 1) * 8) * SA +
                     kh * 16 + ((lane >> 3) & 1) * 8) * 2;
                ldsm_x4(bf[nq], addr);
            }
#pragma unroll
            for (int mi = 0; mi < 2; mi++)
#pragma unroll
                for (int nq = 0; nq < NQ; nq++) {
                    mma_f16(acc[mi][nq * 2],     af[mi], bf[nq][0], bf[nq][1]);
                    mma_f16(acc[mi][nq * 2 + 1], af[mi], bf[nq][2], bf[nq][3]);
                }
        }
        __syncthreads();
    }

    float qv[2][2];
    if (L1) {
#pragma unroll
        for (int mi = 0; mi < 2; mi++) {
            int r0 = row0 + wm0 + mi * 16 + (lane >> 2);
            qv[mi][0] = (r0 < M) ? __ldg(&g_q[r0]) : 0.f;
            qv[mi][1] = (r0 + 8 < M) ? __ldg(&g_q[r0 + 8]) : 0.f;
        }
    }
#pragma unroll
    for (int mi = 0; mi < 2; mi++) {
        int r0 = row0 + wm0 + mi * 16 + (lane >> 2);
#pragma unroll
        for (int nt = 0; nt < 2 * NQ; nt++) {
            int c0 = n0 + wn0 + nt * 8 + (lane & 3) * 2;
            if (L1) {
                float cc0 = __ldg(&g_c1[c0]),   cc1 = __ldg(&g_c1[c0 + 1]);
                float bb0 = __ldg(&bias[c0]),   bb1 = __ldg(&bias[c0 + 1]);
                float ss0 = __ldg(&slope[c0]),  ss1 = __ldg(&slope[c0 + 1]);
#pragma unroll
                for (int h = 0; h < 2; h++) {
                    int r = r0 + h * 8;
                    if (r >= M) continue;
                    float v0 = acc[mi][nt][h * 2]     + qv[mi][h] * cc0 + bb0;
                    float v1 = acc[mi][nt][h * 2 + 1] + qv[mi][h] * cc1 + bb1;
                    v0 = v0 >= 0.f ? v0 : ss0 * v0;
                    v1 = v1 >= 0.f ? v1 : ss1 * v1;
                    __half2 hh = __floats2half2_rn(v0, v1);
                    *(uint32_t*)(Out + (size_t)r * NTOT + c0) = *(uint32_t*)&hh;
                }
            } else {
#pragma unroll
                for (int h = 0; h < 2; h++) {
                    int r = r0 + h * 8;
                    if (r >= M) continue;
                    __half2 hh = __floats2half2_rn(acc[mi][nt][h * 2],
                                                   acc[mi][nt][h * 2 + 1]);
                    *(uint32_t*)(Out + (size_t)r * NTOT + c0) = *(uint32_t*)&hh;
                }
            }
        }
    }
}

// -------------------- gather2: fp16 h2 rows, fused bias+prelu (x8) ----------
__global__ __launch_bounds__(256) void k_gather2(const float* __restrict__ bias,
                                                 const float* __restrict__ slope,
                                                 float* __restrict__ out) {
    const int lane = threadIdx.x & 31;
    const int node = (blockIdx.x * blockDim.x + threadIdx.x) >> 5;
    if (node >= NNODES) return;
    const float dv = g_dinv[node];
    const int e0 = g_off[node], e1 = g_off[node + 1];
    float4 acc = make_float4(0.f, 0.f, 0.f, 0.f);

    auto rowfma = [&](int s, float w) {
        uint2 hv = __ldg((const uint2*)(g_h2 + (size_t)s * OUTD) + lane);
        __half2 p0 = *(__half2*)&hv.x;
        __half2 p1 = *(__half2*)&hv.y;
        float2 f0 = __half22float2(p0);
        float2 f1 = __half22float2(p1);
        acc.x += f0.x * w; acc.y += f0.y * w;
        acc.z += f1.x * w; acc.w += f1.y * w;
    };

    int e = e0;
    for (; e + 8 <= e1; e += 8) {
        int s[8];
        float w[8];
#pragma unroll
        for (int k = 0; k < 8; k++) s[k] = __ldg(&g_src[e + k]);
#pragma unroll
        for (int k = 0; k < 8; k++) w[k] = __ldg(&g_dinv[s[k]]) * dv;
#pragma unroll
        for (int k = 0; k < 8; k++) rowfma(s[k], w[k]);
    }
    for (; e < e1; e++) {
        int s0 = __ldg(&g_src[e]);
        float w0 = __ldg(&g_dinv[s0]) * dv;
        rowfma(s0, w0);
    }
    rowfma(node, dv * dv);

    float4 B = *(const float4*)&bias[lane * 4];
    float4 S = *(const float4*)&slope[lane * 4];
    float r0 = acc.x + B.x, r1 = acc.y + B.y, r2 = acc.z + B.z, r3 = acc.w + B.w;
    float4 o;
    o.x = r0 >= 0.f ? r0 : S.x * r0;
    o.y = r1 >= 0.f ? r1 : S.y * r1;
    o.z = r2 >= 0.f ? r2 : S.z * r2;
    o.w = r3 >= 0.f ? r3 : S.w * r3;
    *(float4*)&out[(size_t)node * OUTD + lane * 4] = o;
}

// -------------------- launch ------------------------------------------------
extern "C" void kernel_launch(void* const* d_in, const int* in_sizes, int n_in,
                              void* d_out, int out_size) {
    const float* x  = (const float*)d_in[0];
    const void*  ei = d_in[1];
    const float* idv = (const float*)d_in[2];
    const float* W1 = (const float*)d_in[3];
    const float* b1 = (const float*)d_in[4];
    const float* a1 = (const float*)d_in[5];
    const float* W2 = (const float*)d_in[6];
    const float* b2 = (const float*)d_in[7];
    const float* a2 = (const float*)d_in[8];
    float* out = (float*)d_out;

    __half *d_ax, *d_h1, *d_h2, *d_w1, *d_w2;
    cudaGetSymbolAddress((void**)&d_ax, g_ax);
    cudaGetSymbolAddress((void**)&d_h1, g_h1);
    cudaGetSymbolAddress((void**)&d_h2, g_h2);
    cudaGetSymbolAddress((void**)&d_w1, g_wt1);
    cudaGetSymbolAddress((void**)&d_w2, g_wt2);

    const int T = 256;
    constexpr int SMEM1 = 2 * (128 + 128) * 40 * 2;   // 40960 B
    constexpr int SMEM2 = 2 * (128 + 64) * 40 * 2;    // 30720 B

    static bool attr_done = false;
    if (!attr_done) {
        cudaFuncSetAttribute(k_mma<INDIM, HID, 128, true>,
                             cudaFuncAttributeMaxDynamicSharedMemorySize, SMEM1);
        cudaFuncSetAttribute(k_mma<HID, OUTD, 64, false>,
                             cudaFuncAttributeMaxDynamicSharedMemorySize, SMEM2);
        attr_done = true;
    }

    {
        constexpr int TOT = NNODES * INDIM / 4 + NNODES +
                            HID * INDIM + OUTD * HID + HID;
        k_prep0<<<(TOT + T - 1) / T, T>>>(x, (const long long*)ei, W1, W2, idv);
    }
    k_deg<<<(NEDGES / 4 + T - 1) / T, T>>>(ei);
    k_scan<<<1, 1024>>>();
    k_csr<<<(NEDGES / 4 + T - 1) / T, T>>>(ei);

    k_gather1<<<(NNODES * 32 + T - 1) / T, T>>>();

    {   // GEMM1: [50000,128] @ [256,128]^T -> h1 fp16 (fused q*c1+b1+prelu)
        dim3 grid(HID / 128, (NNODES + 127) / 128);
        k_mma<INDIM, HID, 128, true><<<grid, 256, SMEM1>>>(
            d_ax, d_w1, b1, a1, d_h1, NNODES);
    }
    {   // GEMM2: [50000,256] @ [128,256]^T -> h2 fp16
        dim3 grid(OUTD / 64, (NNODES + 127) / 128);
        k_mma<HID, OUTD, 64, false><<<grid, 256, SMEM2>>>(
            d_h1, d_w2, nullptr, nullptr, d_h2, NNODES);
    }
    k_gather2<<<(NNODES * 32 + T - 1) / T, T>>>(b2, a2, out);
}